// round 1
// baseline (speedup 1.0000x reference)
#include <cuda_runtime.h>
#include <math.h>

#define BB 2
#define SS 2048
#define DD 1024
#define HH 16
#define HD 64
#define ROWS (BB*SS)

// Scratch (static device globals — no runtime allocation)
__device__ float g_xn[ROWS * DD];
__device__ float g_q[ROWS * DD];
__device__ float g_k[ROWS * DD];
__device__ float g_v[ROWS * DD];
__device__ float g_ctx[ROWS * DD];

// ---------------------------------------------------------------------------
// LayerNorm: one block per row, 256 threads, float4 path
// ---------------------------------------------------------------------------
__global__ void __launch_bounds__(256) ln_kernel(
    const float* __restrict__ x, const float* __restrict__ gamma,
    const float* __restrict__ beta, float* __restrict__ out)
{
    int row = blockIdx.x;
    int t = threadIdx.x;                      // 256 threads, 256 float4 per row
    float4 v = ((const float4*)(x + (size_t)row * DD))[t];
    float s  = v.x + v.y + v.z + v.w;
    float ss = v.x*v.x + v.y*v.y + v.z*v.z + v.w*v.w;

    #pragma unroll
    for (int o = 16; o; o >>= 1) {
        s  += __shfl_xor_sync(0xffffffffu, s,  o);
        ss += __shfl_xor_sync(0xffffffffu, ss, o);
    }
    __shared__ float rs[8], rss[8];
    int w = t >> 5;
    if ((t & 31) == 0) { rs[w] = s; rss[w] = ss; }
    __syncthreads();
    if (t < 32) {
        float a  = (t < 8) ? rs[t]  : 0.f;
        float aa = (t < 8) ? rss[t] : 0.f;
        #pragma unroll
        for (int o = 4; o; o >>= 1) {
            a  += __shfl_xor_sync(0xffffffffu, a,  o);
            aa += __shfl_xor_sync(0xffffffffu, aa, o);
        }
        if (t == 0) { rs[0] = a; rss[0] = aa; }
    }
    __syncthreads();
    float mean = rs[0] * (1.0f / DD);
    float var  = rss[0] * (1.0f / DD) - mean * mean;
    float rstd = rsqrtf(var + 1e-12f);

    float4 g  = ((const float4*)gamma)[t];
    float4 bt = ((const float4*)beta)[t];
    float4 r;
    r.x = (v.x - mean) * rstd * g.x + bt.x;
    r.y = (v.y - mean) * rstd * g.y + bt.y;
    r.z = (v.z - mean) * rstd * g.z + bt.z;
    r.w = (v.w - mean) * rstd * g.w + bt.w;
    ((float4*)(out + (size_t)row * DD))[t] = r;
}

// ---------------------------------------------------------------------------
// GEMM-NT: C[M,N] = A[M,K] @ W[N,K]^T + bias[N] (+ residual)
// BM=BN=128, BK=8, 256 threads, 8x8 per-thread microtile
// ---------------------------------------------------------------------------
template<bool RESID>
__global__ void __launch_bounds__(256) gemm_nt(
    const float* __restrict__ A, const float* __restrict__ W,
    const float* __restrict__ bias, const float* __restrict__ resid,
    float* __restrict__ C, int M, int N, int K)
{
    __shared__ float As[8][128];
    __shared__ float Bs[8][128];

    int tid = threadIdx.x;
    int tx = tid & 15;           // 0..15 -> 8 cols each
    int ty = tid >> 4;           // 0..15 -> 8 rows each
    int rowBase = blockIdx.y * 128;
    int colBase = blockIdx.x * 128;

    int lr = tid >> 1;           // 0..127 tile row
    int lk = (tid & 1) * 4;      // 0 or 4 (k offset)

    const float* Ap = A + (size_t)(rowBase + lr) * K + lk;
    const float* Wp = W + (size_t)(colBase + lr) * K + lk;

    float acc[8][8];
    #pragma unroll
    for (int i = 0; i < 8; i++)
        #pragma unroll
        for (int j = 0; j < 8; j++) acc[i][j] = 0.f;

    for (int k0 = 0; k0 < K; k0 += 8) {
        float4 a4 = *(const float4*)(Ap + k0);
        float4 w4 = *(const float4*)(Wp + k0);
        As[lk + 0][lr] = a4.x; As[lk + 1][lr] = a4.y;
        As[lk + 2][lr] = a4.z; As[lk + 3][lr] = a4.w;
        Bs[lk + 0][lr] = w4.x; Bs[lk + 1][lr] = w4.y;
        Bs[lk + 2][lr] = w4.z; Bs[lk + 3][lr] = w4.w;
        __syncthreads();

        #pragma unroll
        for (int kk = 0; kk < 8; kk++) {
            float a[8], b[8];
            *(float4*)(a)     = *(const float4*)&As[kk][ty * 8];
            *(float4*)(a + 4) = *(const float4*)&As[kk][ty * 8 + 4];
            *(float4*)(b)     = *(const float4*)&Bs[kk][tx * 8];
            *(float4*)(b + 4) = *(const float4*)&Bs[kk][tx * 8 + 4];
            #pragma unroll
            for (int i = 0; i < 8; i++)
                #pragma unroll
                for (int j = 0; j < 8; j++)
                    acc[i][j] += a[i] * b[j];
        }
        __syncthreads();
    }

    float bf[8];
    *(float4*)(bf)     = *(const float4*)(bias + colBase + tx * 8);
    *(float4*)(bf + 4) = *(const float4*)(bias + colBase + tx * 8 + 4);

    #pragma unroll
    for (int i = 0; i < 8; i++) {
        int r = rowBase + ty * 8 + i;
        float* Crow = C + (size_t)r * N + colBase + tx * 8;
        float4 o0, o1;
        o0.x = acc[i][0] + bf[0]; o0.y = acc[i][1] + bf[1];
        o0.z = acc[i][2] + bf[2]; o0.w = acc[i][3] + bf[3];
        o1.x = acc[i][4] + bf[4]; o1.y = acc[i][5] + bf[5];
        o1.z = acc[i][6] + bf[6]; o1.w = acc[i][7] + bf[7];
        if (RESID) {
            const float* Rrow = resid + (size_t)r * N + colBase + tx * 8;
            float4 r0 = *(const float4*)(Rrow);
            float4 r1 = *(const float4*)(Rrow + 4);
            o0.x += r0.x; o0.y += r0.y; o0.z += r0.z; o0.w += r0.w;
            o1.x += r1.x; o1.y += r1.y; o1.z += r1.z; o1.w += r1.w;
        }
        *(float4*)(Crow)     = o0;
        *(float4*)(Crow + 4) = o1;
    }
}

// ---------------------------------------------------------------------------
// Flash attention (fp32): grid (S/128, H, B), 128 threads, 1 q-row per thread
// ---------------------------------------------------------------------------
__global__ void __launch_bounds__(128) attn_kernel(const float* __restrict__ mask)
{
    extern __shared__ float sm[];
    float* Qs = sm;                    // 128 x 64
    float* Ks = Qs + 128 * 64;         // 64 x 64
    float* Vs = Ks + 64 * 64;          // 64 x 64
    float* Ms = Vs + 64 * 64;          // 64

    int t  = threadIdx.x;
    int b  = blockIdx.z;
    int h  = blockIdx.y;
    int qt = blockIdx.x;

    int qrow0 = b * SS + qt * 128;
    const float* qbase = g_q + (size_t)qrow0 * DD + h * HD;

    // stage Q tile (coalesced)
    for (int idx = t; idx < 128 * 16; idx += 128) {
        int r = idx >> 4, d4 = idx & 15;
        ((float4*)Qs)[idx] = *(const float4*)(qbase + (size_t)r * DD + d4 * 4);
    }

    float m = -1e30f, l = 0.f;
    float o[64];
    #pragma unroll
    for (int d = 0; d < 64; d++) o[d] = 0.f;
    float s[64];

    for (int kt = 0; kt < SS / 64; kt++) {
        __syncthreads();
        int krow0 = b * SS + kt * 64;
        const float* kbase = g_k + (size_t)krow0 * DD + h * HD;
        const float* vbase = g_v + (size_t)krow0 * DD + h * HD;
        for (int idx = t; idx < 64 * 16; idx += 128) {
            int r = idx >> 4, d4 = idx & 15;
            ((float4*)Ks)[idx] = *(const float4*)(kbase + (size_t)r * DD + d4 * 4);
            ((float4*)Vs)[idx] = *(const float4*)(vbase + (size_t)r * DD + d4 * 4);
        }
        if (t < 64) Ms[t] = mask[b * SS + kt * 64 + t];
        __syncthreads();

        #pragma unroll
        for (int j = 0; j < 64; j++) s[j] = 0.f;

        // scores: s[j] += q . k_j   (q float4 in regs, Ks broadcast LDS.128)
        #pragma unroll
        for (int d4 = 0; d4 < 16; d4++) {
            float4 q = ((const float4*)Qs)[t * 16 + d4];
            #pragma unroll
            for (int j = 0; j < 64; j++) {
                float4 k = ((const float4*)Ks)[j * 16 + d4];
                s[j] += q.x * k.x + q.y * k.y + q.z * k.z + q.w * k.w;
            }
        }

        float mt = m;
        #pragma unroll
        for (int j = 0; j < 64; j++) {
            s[j] = s[j] * 0.125f + Ms[j];
            mt = fmaxf(mt, s[j]);
        }
        float corr = __expf(m - mt);
        m = mt;
        l *= corr;
        #pragma unroll
        for (int d = 0; d < 64; d++) o[d] *= corr;

        #pragma unroll
        for (int j = 0; j < 64; j++) {
            float p = __expf(s[j] - m);
            l += p;
            #pragma unroll
            for (int d4 = 0; d4 < 16; d4++) {
                float4 v = ((const float4*)Vs)[j * 16 + d4];
                o[d4 * 4 + 0] += p * v.x;
                o[d4 * 4 + 1] += p * v.y;
                o[d4 * 4 + 2] += p * v.z;
                o[d4 * 4 + 3] += p * v.w;
            }
        }
    }

    float inv = 1.f / l;
    __syncthreads();                 // all Qs reads done
    #pragma unroll
    for (int d = 0; d < 64; d++) Qs[t * 64 + d] = o[d] * inv;
    __syncthreads();

    float* obase = g_ctx + (size_t)qrow0 * DD + h * HD;
    for (int idx = t; idx < 128 * 16; idx += 128) {
        int r = idx >> 4, d4 = idx & 15;
        *(float4*)(obase + (size_t)r * DD + d4 * 4) = ((const float4*)Qs)[idx];
    }
}

// ---------------------------------------------------------------------------
// Launcher
// ---------------------------------------------------------------------------
extern "C" void kernel_launch(void* const* d_in, const int* in_sizes, int n_in,
                              void* d_out, int out_size)
{
    const float* hidden = (const float*)d_in[0];
    const float* mask   = (const float*)d_in[1];
    const float* gamma  = (const float*)d_in[2];
    const float* beta   = (const float*)d_in[3];
    const float* wq = (const float*)d_in[4];
    const float* bq = (const float*)d_in[5];
    const float* wk = (const float*)d_in[6];
    const float* bk = (const float*)d_in[7];
    const float* wv = (const float*)d_in[8];
    const float* bv = (const float*)d_in[9];
    const float* wo = (const float*)d_in[10];
    const float* bo = (const float*)d_in[11];
    float* out = (float*)d_out;

    void *p_xn, *p_q, *p_k, *p_v, *p_ctx;
    cudaGetSymbolAddress(&p_xn, g_xn);
    cudaGetSymbolAddress(&p_q,  g_q);
    cudaGetSymbolAddress(&p_k,  g_k);
    cudaGetSymbolAddress(&p_v,  g_v);
    cudaGetSymbolAddress(&p_ctx, g_ctx);
    float* xn  = (float*)p_xn;
    float* q   = (float*)p_q;
    float* k   = (float*)p_k;
    float* v   = (float*)p_v;
    float* ctx = (float*)p_ctx;

    // 1. LayerNorm
    ln_kernel<<<ROWS, 256>>>(hidden, gamma, beta, xn);

    // 2. QKV projections
    dim3 ggrid(DD / 128, ROWS / 128);
    gemm_nt<false><<<ggrid, 256>>>(xn, wq, bq, nullptr, q, ROWS, DD, DD);
    gemm_nt<false><<<ggrid, 256>>>(xn, wk, bk, nullptr, k, ROWS, DD, DD);
    gemm_nt<false><<<ggrid, 256>>>(xn, wv, bv, nullptr, v, ROWS, DD, DD);

    // 3. Attention
    int smem = (128 * 64 + 64 * 64 + 64 * 64 + 64) * sizeof(float);
    cudaFuncSetAttribute(attn_kernel, cudaFuncAttributeMaxDynamicSharedMemorySize, smem);
    attn_kernel<<<dim3(SS / 128, HH, BB), 128, smem>>>(mask);

    // 4. Output projection + bias + residual
    gemm_nt<true><<<ggrid, 256>>>(ctx, wo, bo, hidden, out, ROWS, DD, DD);
}

// round 3
// speedup vs baseline: 1.2339x; 1.2339x over previous
#include <cuda_runtime.h>
#include <cstdint>
#include <math.h>

#define BB 2
#define SS 2048
#define DD 1024
#define HH 16
#define HD 64
#define ROWS (BB*SS)

// Scratch (static device globals — no runtime allocation)
__device__ float g_xn[ROWS * DD];
__device__ float g_q[ROWS * DD];
__device__ float g_k[ROWS * DD];
__device__ float g_v[ROWS * DD];
__device__ float g_ctx[ROWS * DD];
__device__ float g_wr[4 * DD * DD];   // tf32-rounded wq,wk,wv,wo

// ---------------------------------------------------------------------------
// helpers
// ---------------------------------------------------------------------------
__device__ __forceinline__ uint32_t smem_u32(const void* p) {
    uint32_t a;
    asm("{ .reg .u64 t; cvta.to.shared.u64 t, %1; cvt.u32.u64 %0, t; }"
        : "=r"(a) : "l"(p));
    return a;
}

__device__ __forceinline__ float to_tf32(float x) {
    uint32_t u;
    asm("cvt.rna.tf32.f32 %0, %1;" : "=r"(u) : "f"(x));
    return __uint_as_float(u);
}

#define CP_ASYNC16(smem_addr, gptr) \
    asm volatile("cp.async.cg.shared.global [%0], [%1], 16;" \
                 :: "r"(smem_addr), "l"(gptr) : "memory")
#define CP_COMMIT() asm volatile("cp.async.commit_group;" ::: "memory")
#define CP_WAIT(N)  asm volatile("cp.async.wait_group %0;" :: "n"(N) : "memory")

__device__ __forceinline__ void mma_tf32(float* c, const uint32_t* a, const uint32_t* b) {
    asm volatile(
        "mma.sync.aligned.m16n8k8.row.col.f32.tf32.tf32.f32 "
        "{%0,%1,%2,%3}, {%4,%5,%6,%7}, {%8,%9}, {%0,%1,%2,%3};"
        : "+f"(c[0]), "+f"(c[1]), "+f"(c[2]), "+f"(c[3])
        : "r"(a[0]), "r"(a[1]), "r"(a[2]), "r"(a[3]), "r"(b[0]), "r"(b[1]));
}

// ---------------------------------------------------------------------------
// Weight prep: round all 4 weight matrices to tf32 (rna)
// ---------------------------------------------------------------------------
__global__ void __launch_bounds__(256) wprep_kernel(
    const float* __restrict__ wq, const float* __restrict__ wk,
    const float* __restrict__ wv, const float* __restrict__ wo,
    float* __restrict__ dst)
{
    int i = blockIdx.x * 256 + threadIdx.x;        // float4 index
    const float* srcs[4] = {wq, wk, wv, wo};
    int which = i / (DD * DD / 4);
    int off   = i % (DD * DD / 4);
    float4 v = ((const float4*)srcs[which])[off];
    v.x = to_tf32(v.x); v.y = to_tf32(v.y);
    v.z = to_tf32(v.z); v.w = to_tf32(v.w);
    ((float4*)dst)[i] = v;
}

// ---------------------------------------------------------------------------
// LayerNorm: one block per row, 256 threads; output rounded to tf32
// ---------------------------------------------------------------------------
__global__ void __launch_bounds__(256) ln_kernel(
    const float* __restrict__ x, const float* __restrict__ gamma,
    const float* __restrict__ beta, float* __restrict__ out)
{
    int row = blockIdx.x;
    int t = threadIdx.x;
    float4 v = ((const float4*)(x + (size_t)row * DD))[t];
    float s  = v.x + v.y + v.z + v.w;
    float ss = v.x*v.x + v.y*v.y + v.z*v.z + v.w*v.w;

    #pragma unroll
    for (int o = 16; o; o >>= 1) {
        s  += __shfl_xor_sync(0xffffffffu, s,  o);
        ss += __shfl_xor_sync(0xffffffffu, ss, o);
    }
    __shared__ float rs[8], rss[8];
    int w = t >> 5;
    if ((t & 31) == 0) { rs[w] = s; rss[w] = ss; }
    __syncthreads();
    if (t < 32) {
        float a  = (t < 8) ? rs[t]  : 0.f;
        float aa = (t < 8) ? rss[t] : 0.f;
        #pragma unroll
        for (int o = 4; o; o >>= 1) {
            a  += __shfl_xor_sync(0xffffffffu, a,  o);
            aa += __shfl_xor_sync(0xffffffffu, aa, o);
        }
        if (t == 0) { rs[0] = a; rss[0] = aa; }
    }
    __syncthreads();
    float mean = rs[0] * (1.0f / DD);
    float var  = rss[0] * (1.0f / DD) - mean * mean;
    float rstd = rsqrtf(var + 1e-12f);

    float4 g  = ((const float4*)gamma)[t];
    float4 bt = ((const float4*)beta)[t];
    float4 r;
    r.x = to_tf32((v.x - mean) * rstd * g.x + bt.x);
    r.y = to_tf32((v.y - mean) * rstd * g.y + bt.y);
    r.z = to_tf32((v.z - mean) * rstd * g.z + bt.z);
    r.w = to_tf32((v.w - mean) * rstd * g.w + bt.w);
    ((float4*)(out + (size_t)row * DD))[t] = r;
}

// ---------------------------------------------------------------------------
// mma.sync tf32 GEMM-NT: C[M,N] = A[M,K] @ W[N,K]^T + bias (+ residual)
// Block tile 128x128, 4 warps (2x2), warp tile 64x64 (4 m-tiles x 8 n-tiles).
// BK=16, cp.async double-buffered.
// ---------------------------------------------------------------------------
#define SKW 20   // smem row stride (16 + 4 pad) -> conflict-free frag loads

template<bool RESID>
__global__ void __launch_bounds__(128) gemm_mma(
    const float* __restrict__ A, const float* __restrict__ W,
    const float* __restrict__ bias, const float* __restrict__ resid,
    float* __restrict__ C)
{
    __shared__ __align__(16) float sA[2][128 * SKW];
    __shared__ __align__(16) float sB[2][128 * SKW];

    int tid  = threadIdx.x;
    int lane = tid & 31;
    int wid  = tid >> 5;
    int wm = (wid & 1) * 64;
    int wn = (wid >> 1) * 64;
    int rowBase = blockIdx.y * 128;
    int colBase = blockIdx.x * 128;

    int gid = lane >> 2;   // groupID 0..7
    int tig = lane & 3;    // threadID in group 0..3

    const float* gA = A + (size_t)(rowBase + tid) * DD;
    const float* gW = W + (size_t)(colBase + tid) * DD;

    float acc[4][8][4];
    #pragma unroll
    for (int mt = 0; mt < 4; mt++)
        #pragma unroll
        for (int nt = 0; nt < 8; nt++)
            #pragma unroll
            for (int r = 0; r < 4; r++) acc[mt][nt][r] = 0.f;

    uint32_t saw[2], sbw[2];
    saw[0] = smem_u32(&sA[0][tid * SKW]); saw[1] = smem_u32(&sA[1][tid * SKW]);
    sbw[0] = smem_u32(&sB[0][tid * SKW]); sbw[1] = smem_u32(&sB[1][tid * SKW]);

    // prefetch chunk 0
    {
        #pragma unroll
        for (int j = 0; j < 4; j++) {
            CP_ASYNC16(saw[0] + j * 16, gA + j * 4);
            CP_ASYNC16(sbw[0] + j * 16, gW + j * 4);
        }
        CP_COMMIT();
    }

    const int NCHUNK = DD / 16;   // 64
    for (int c = 0; c < NCHUNK; c++) {
        int buf = c & 1;
        if (c + 1 < NCHUNK) {
            const float* pa = gA + (c + 1) * 16;
            const float* pw = gW + (c + 1) * 16;
            int nb = buf ^ 1;
            #pragma unroll
            for (int j = 0; j < 4; j++) {
                CP_ASYNC16(saw[nb] + j * 16, pa + j * 4);
                CP_ASYNC16(sbw[nb] + j * 16, pw + j * 4);
            }
            CP_COMMIT();
            CP_WAIT(1);
        } else {
            CP_WAIT(0);
        }
        __syncthreads();

        const float* pa = sA[buf];
        const float* pb = sB[buf];
        #pragma unroll
        for (int ks = 0; ks < 2; ks++) {
            int kb = ks * 8 + tig;
            uint32_t af[4][4];
            #pragma unroll
            for (int mt = 0; mt < 4; mt++) {
                int r = wm + mt * 16 + gid;
                af[mt][0] = __float_as_uint(pa[r * SKW + kb]);
                af[mt][1] = __float_as_uint(pa[(r + 8) * SKW + kb]);
                af[mt][2] = __float_as_uint(pa[r * SKW + kb + 4]);
                af[mt][3] = __float_as_uint(pa[(r + 8) * SKW + kb + 4]);
            }
            uint32_t bf[8][2];
            #pragma unroll
            for (int nt = 0; nt < 8; nt++) {
                int n = wn + nt * 8 + gid;
                bf[nt][0] = __float_as_uint(pb[n * SKW + kb]);
                bf[nt][1] = __float_as_uint(pb[n * SKW + kb + 4]);
            }
            #pragma unroll
            for (int mt = 0; mt < 4; mt++)
                #pragma unroll
                for (int nt = 0; nt < 8; nt++)
                    mma_tf32(acc[mt][nt], af[mt], bf[nt]);
        }
        __syncthreads();
    }

    // Epilogue: c0,c1 -> row r, cols col..col+1 ; c2,c3 -> row r+8
    #pragma unroll
    for (int mt = 0; mt < 4; mt++) {
        int r0 = rowBase + wm + mt * 16 + gid;
        #pragma unroll
        for (int nt = 0; nt < 8; nt++) {
            int col = colBase + wn + nt * 8 + tig * 2;
            float2 b2 = *(const float2*)(bias + col);
            float2 o0, o1;
            o0.x = acc[mt][nt][0] + b2.x; o0.y = acc[mt][nt][1] + b2.y;
            o1.x = acc[mt][nt][2] + b2.x; o1.y = acc[mt][nt][3] + b2.y;
            if (RESID) {
                float2 r0v = *(const float2*)(resid + (size_t)r0 * DD + col);
                float2 r1v = *(const float2*)(resid + (size_t)(r0 + 8) * DD + col);
                o0.x += r0v.x; o0.y += r0v.y;
                o1.x += r1v.x; o1.y += r1v.y;
            }
            *(float2*)(C + (size_t)r0 * DD + col)       = o0;
            *(float2*)(C + (size_t)(r0 + 8) * DD + col) = o1;
        }
    }
}

// ---------------------------------------------------------------------------
// Flash attention v2 (fp32): 256 threads = 128 q rows x 2 half-threads.
// KT=32 keys/tile. grid (S/128, H, B). 2 CTAs/SM.
// ctx output rounded to tf32 (it feeds the tf32 O-projection).
// ---------------------------------------------------------------------------
#define QPAD 68
__global__ void __launch_bounds__(256, 2) attn_kernel(const float* __restrict__ mask)
{
    extern __shared__ float sm[];
    float* Qs = sm;                      // 128 x QPAD
    float* Ks = Qs + 128 * QPAD;         // 32 x 64
    float* Vs = Ks + 32 * 64;            // 32 x 64
    float* Ms = Vs + 32 * 64;            // 32

    int t    = threadIdx.x;
    int qr   = t >> 1;
    int half = t & 1;
    int b  = blockIdx.z;
    int h  = blockIdx.y;
    int qt = blockIdx.x;

    int qrow0 = b * SS + qt * 128;
    const float* qbase = g_q + (size_t)qrow0 * DD + h * HD;

    #pragma unroll
    for (int i = 0; i < 8; i++) {
        int idx = t + i * 256;
        int r = idx >> 4, d4 = idx & 15;
        *(float4*)(Qs + r * QPAD + d4 * 4) =
            *(const float4*)(qbase + (size_t)r * DD + d4 * 4);
    }

    const float* qrow = Qs + qr * QPAD + half * 32;

    float m = -1e30f, l = 0.f;
    float o[32];
    #pragma unroll
    for (int d = 0; d < 32; d++) o[d] = 0.f;

    for (int kt = 0; kt < SS / 32; kt++) {
        __syncthreads();
        int krow0 = b * SS + kt * 32;
        const float* kbase = g_k + (size_t)krow0 * DD + h * HD;
        const float* vbase = g_v + (size_t)krow0 * DD + h * HD;
        #pragma unroll
        for (int i = 0; i < 2; i++) {
            int idx = t + i * 256;
            int r = idx >> 4, d4 = idx & 15;
            ((float4*)Ks)[idx] = *(const float4*)(kbase + (size_t)r * DD + d4 * 4);
            ((float4*)Vs)[idx] = *(const float4*)(vbase + (size_t)r * DD + d4 * 4);
        }
        if (t < 32) Ms[t] = mask[b * SS + kt * 32 + t];
        __syncthreads();

        float s[32];
        #pragma unroll
        for (int j = 0; j < 32; j++) s[j] = 0.f;

        #pragma unroll
        for (int d4 = 0; d4 < 8; d4++) {
            float4 q = ((const float4*)qrow)[d4];
            #pragma unroll
            for (int j = 0; j < 32; j++) {
                float4 k = *(const float4*)(Ks + j * 64 + half * 32 + d4 * 4);
                s[j] += q.x * k.x + q.y * k.y + q.z * k.z + q.w * k.w;
            }
        }
        #pragma unroll
        for (int j = 0; j < 32; j++)
            s[j] += __shfl_xor_sync(0xffffffffu, s[j], 1);

        float mt = m;
        #pragma unroll
        for (int j = 0; j < 32; j++) {
            s[j] = s[j] * 0.125f + Ms[j];
            mt = fmaxf(mt, s[j]);
        }
        float corr = __expf(m - mt);
        m = mt;
        l *= corr;
        #pragma unroll
        for (int d = 0; d < 32; d++) o[d] *= corr;

        #pragma unroll
        for (int j = 0; j < 32; j++) {
            float p = __expf(s[j] - m);
            l += p;
            #pragma unroll
            for (int d4 = 0; d4 < 8; d4++) {
                float4 v = *(const float4*)(Vs + j * 64 + half * 32 + d4 * 4);
                o[d4 * 4 + 0] += p * v.x;
                o[d4 * 4 + 1] += p * v.y;
                o[d4 * 4 + 2] += p * v.z;
                o[d4 * 4 + 3] += p * v.w;
            }
        }
    }

    float inv = 1.f / l;
    float* obase = g_ctx + (size_t)(qrow0 + qr) * DD + h * HD + half * 32;
    #pragma unroll
    for (int d4 = 0; d4 < 8; d4++) {
        float4 r;
        r.x = to_tf32(o[d4 * 4 + 0] * inv);
        r.y = to_tf32(o[d4 * 4 + 1] * inv);
        r.z = to_tf32(o[d4 * 4 + 2] * inv);
        r.w = to_tf32(o[d4 * 4 + 3] * inv);
        *(float4*)(obase + d4 * 4) = r;
    }
}

// ---------------------------------------------------------------------------
// Launcher
// ---------------------------------------------------------------------------
extern "C" void kernel_launch(void* const* d_in, const int* in_sizes, int n_in,
                              void* d_out, int out_size)
{
    const float* hidden = (const float*)d_in[0];
    const float* mask   = (const float*)d_in[1];
    const float* gamma  = (const float*)d_in[2];
    const float* beta   = (const float*)d_in[3];
    const float* wq = (const float*)d_in[4];
    const float* bq = (const float*)d_in[5];
    const float* wk = (const float*)d_in[6];
    const float* bk = (const float*)d_in[7];
    const float* wv = (const float*)d_in[8];
    const float* bv = (const float*)d_in[9];
    const float* wo = (const float*)d_in[10];
    const float* bo = (const float*)d_in[11];
    float* out = (float*)d_out;

    void *p_xn, *p_q, *p_k, *p_v, *p_ctx, *p_wr;
    cudaGetSymbolAddress(&p_xn, g_xn);
    cudaGetSymbolAddress(&p_q,  g_q);
    cudaGetSymbolAddress(&p_k,  g_k);
    cudaGetSymbolAddress(&p_v,  g_v);
    cudaGetSymbolAddress(&p_ctx, g_ctx);
    cudaGetSymbolAddress(&p_wr, g_wr);
    float* xn  = (float*)p_xn;
    float* q   = (float*)p_q;
    float* k   = (float*)p_k;
    float* v   = (float*)p_v;
    float* ctx = (float*)p_ctx;
    float* wr  = (float*)p_wr;

    // 0. Round weights to tf32 (unbiased rna)
    wprep_kernel<<<4 * DD * DD / 4 / 256, 256>>>(wq, wk, wv, wo, wr);

    // 1. LayerNorm (outputs tf32-rounded)
    ln_kernel<<<ROWS, 256>>>(hidden, gamma, beta, xn);

    // 2. QKV projections (mma.sync tf32)
    dim3 ggrid(DD / 128, ROWS / 128);
    gemm_mma<false><<<ggrid, 128>>>(xn, wr + 0 * DD * DD, bq, nullptr, q);
    gemm_mma<false><<<ggrid, 128>>>(xn, wr + 1 * DD * DD, bk, nullptr, k);
    gemm_mma<false><<<ggrid, 128>>>(xn, wr + 2 * DD * DD, bv, nullptr, v);

    // 3. Attention (fp32, 2 CTAs/SM)
    int smem = (128 * QPAD + 32 * 64 * 2 + 32) * sizeof(float);
    cudaFuncSetAttribute(attn_kernel, cudaFuncAttributeMaxDynamicSharedMemorySize, smem);
    attn_kernel<<<dim3(SS / 128, HH, BB), 256, smem>>>(mask);

    // 4. Output projection + bias + residual (mma.sync tf32)
    gemm_mma<true><<<ggrid, 128>>>(ctx, wr + 3 * DD * DD, bo, hidden, out);
}

// round 4
// speedup vs baseline: 4.6168x; 3.7417x over previous
#include <cuda_runtime.h>
#include <cstdint>
#include <math.h>

#define BB 2
#define SS 2048
#define DD 1024
#define HH 16
#define HD 64
#define ROWS (BB*SS)

// Scratch (static device globals — no runtime allocation)
__device__ float g_xn[ROWS * DD];
__device__ float g_qkv[ROWS * 3 * DD];
__device__ float g_ctx[ROWS * DD];
__device__ float g_wr[4 * DD * DD];   // tf32-rounded wq,wk,wv,wo
__device__ float g_bqkv[3 * DD];

// ---------------------------------------------------------------------------
// helpers
// ---------------------------------------------------------------------------
__device__ __forceinline__ uint32_t smem_u32(const void* p) {
    uint32_t a;
    asm("{ .reg .u64 t; cvta.to.shared.u64 t, %1; cvt.u32.u64 %0, t; }"
        : "=r"(a) : "l"(p));
    return a;
}

__device__ __forceinline__ float to_tf32(float x) {
    uint32_t u;
    asm("cvt.rna.tf32.f32 %0, %1;" : "=r"(u) : "f"(x));
    return __uint_as_float(u);
}

#define CP_ASYNC16(smem_addr, gptr) \
    asm volatile("cp.async.cg.shared.global [%0], [%1], 16;" \
                 :: "r"(smem_addr), "l"(gptr) : "memory")
#define CP_COMMIT() asm volatile("cp.async.commit_group;" ::: "memory")
#define CP_WAIT(N)  asm volatile("cp.async.wait_group %0;" :: "n"(N) : "memory")

__device__ __forceinline__ void mma_tf32(float* c, const uint32_t* a, const uint32_t* b) {
    asm volatile(
        "mma.sync.aligned.m16n8k8.row.col.f32.tf32.tf32.f32 "
        "{%0,%1,%2,%3}, {%4,%5,%6,%7}, {%8,%9}, {%0,%1,%2,%3};"
        : "+f"(c[0]), "+f"(c[1]), "+f"(c[2]), "+f"(c[3])
        : "r"(a[0]), "r"(a[1]), "r"(a[2]), "r"(a[3]), "r"(b[0]), "r"(b[1]));
}

// ---------------------------------------------------------------------------
// Weight prep: round all 4 weight matrices to tf32 (rna)
// ---------------------------------------------------------------------------
__global__ void __launch_bounds__(256) wprep_kernel(
    const float* __restrict__ wq, const float* __restrict__ wk,
    const float* __restrict__ wv, const float* __restrict__ wo,
    float* __restrict__ dst)
{
    int i = blockIdx.x * 256 + threadIdx.x;        // float4 index
    const float* srcs[4] = {wq, wk, wv, wo};
    int which = i / (DD * DD / 4);
    int off   = i % (DD * DD / 4);
    float4 v = ((const float4*)srcs[which])[off];
    v.x = to_tf32(v.x); v.y = to_tf32(v.y);
    v.z = to_tf32(v.z); v.w = to_tf32(v.w);
    ((float4*)dst)[i] = v;
}

__global__ void __launch_bounds__(256) bprep_kernel(
    const float* __restrict__ bq, const float* __restrict__ bk,
    const float* __restrict__ bv, float* __restrict__ dst)
{
    int i = blockIdx.x * 256 + threadIdx.x;        // 0..3071
    const float* s = (i < DD) ? bq : ((i < 2 * DD) ? bk : bv);
    dst[i] = s[i & (DD - 1)];
}

// ---------------------------------------------------------------------------
// LayerNorm: one block per row; output rounded to tf32
// ---------------------------------------------------------------------------
__global__ void __launch_bounds__(256) ln_kernel(
    const float* __restrict__ x, const float* __restrict__ gamma,
    const float* __restrict__ beta, float* __restrict__ out)
{
    int row = blockIdx.x;
    int t = threadIdx.x;
    float4 v = ((const float4*)(x + (size_t)row * DD))[t];
    float s  = v.x + v.y + v.z + v.w;
    float ss = v.x*v.x + v.y*v.y + v.z*v.z + v.w*v.w;

    #pragma unroll
    for (int o = 16; o; o >>= 1) {
        s  += __shfl_xor_sync(0xffffffffu, s,  o);
        ss += __shfl_xor_sync(0xffffffffu, ss, o);
    }
    __shared__ float rs[8], rss[8];
    int w = t >> 5;
    if ((t & 31) == 0) { rs[w] = s; rss[w] = ss; }
    __syncthreads();
    if (t < 32) {
        float a  = (t < 8) ? rs[t]  : 0.f;
        float aa = (t < 8) ? rss[t] : 0.f;
        #pragma unroll
        for (int o = 4; o; o >>= 1) {
            a  += __shfl_xor_sync(0xffffffffu, a,  o);
            aa += __shfl_xor_sync(0xffffffffu, aa, o);
        }
        if (t == 0) { rs[0] = a; rss[0] = aa; }
    }
    __syncthreads();
    float mean = rs[0] * (1.0f / DD);
    float var  = rss[0] * (1.0f / DD) - mean * mean;
    float rstd = rsqrtf(var + 1e-12f);

    float4 g  = ((const float4*)gamma)[t];
    float4 bt = ((const float4*)beta)[t];
    float4 r;
    r.x = to_tf32((v.x - mean) * rstd * g.x + bt.x);
    r.y = to_tf32((v.y - mean) * rstd * g.y + bt.y);
    r.z = to_tf32((v.z - mean) * rstd * g.z + bt.z);
    r.w = to_tf32((v.w - mean) * rstd * g.w + bt.w);
    ((float4*)(out + (size_t)row * DD))[t] = r;
}

// ---------------------------------------------------------------------------
// mma.sync tf32 GEMM-NT: C[M,·] = A[M,K] @ W[N,K]^T + bias (+ residual)
// Block tile 128x128, 4 warps (2x2), warp tile 64x64. BK=16, double-buffered.
// lda/ldc runtime; W row-major [Ntot,K] contiguous.
// ---------------------------------------------------------------------------
#define SKW 20

template<bool RESID, bool ROUND>
__global__ void __launch_bounds__(128) gemm_mma(
    const float* __restrict__ A, const float* __restrict__ W,
    const float* __restrict__ bias, const float* __restrict__ resid,
    float* __restrict__ C, int lda, int ldc)
{
    __shared__ __align__(16) float sA[2][128 * SKW];
    __shared__ __align__(16) float sB[2][128 * SKW];

    int tid  = threadIdx.x;
    int lane = tid & 31;
    int wid  = tid >> 5;
    int wm = (wid & 1) * 64;
    int wn = (wid >> 1) * 64;
    int rowBase = blockIdx.y * 128;
    int colBase = blockIdx.x * 128;

    int gid = lane >> 2;
    int tig = lane & 3;

    const float* gA = A + (size_t)(rowBase + tid) * lda;
    const float* gW = W + (size_t)(colBase + tid) * DD;

    float acc[4][8][4];
    #pragma unroll
    for (int mt = 0; mt < 4; mt++)
        #pragma unroll
        for (int nt = 0; nt < 8; nt++)
            #pragma unroll
            for (int r = 0; r < 4; r++) acc[mt][nt][r] = 0.f;

    uint32_t saw[2], sbw[2];
    saw[0] = smem_u32(&sA[0][tid * SKW]); saw[1] = smem_u32(&sA[1][tid * SKW]);
    sbw[0] = smem_u32(&sB[0][tid * SKW]); sbw[1] = smem_u32(&sB[1][tid * SKW]);

    {
        #pragma unroll
        for (int j = 0; j < 4; j++) {
            CP_ASYNC16(saw[0] + j * 16, gA + j * 4);
            CP_ASYNC16(sbw[0] + j * 16, gW + j * 4);
        }
        CP_COMMIT();
    }

    const int NCHUNK = DD / 16;   // 64
    for (int c = 0; c < NCHUNK; c++) {
        int buf = c & 1;
        if (c + 1 < NCHUNK) {
            const float* pa = gA + (c + 1) * 16;
            const float* pw = gW + (c + 1) * 16;
            int nb = buf ^ 1;
            #pragma unroll
            for (int j = 0; j < 4; j++) {
                CP_ASYNC16(saw[nb] + j * 16, pa + j * 4);
                CP_ASYNC16(sbw[nb] + j * 16, pw + j * 4);
            }
            CP_COMMIT();
            CP_WAIT(1);
        } else {
            CP_WAIT(0);
        }
        __syncthreads();

        const float* pa = sA[buf];
        const float* pb = sB[buf];
        #pragma unroll
        for (int ks = 0; ks < 2; ks++) {
            int kb = ks * 8 + tig;
            uint32_t af[4][4];
            #pragma unroll
            for (int mt = 0; mt < 4; mt++) {
                int r = wm + mt * 16 + gid;
                af[mt][0] = __float_as_uint(pa[r * SKW + kb]);
                af[mt][1] = __float_as_uint(pa[(r + 8) * SKW + kb]);
                af[mt][2] = __float_as_uint(pa[r * SKW + kb + 4]);
                af[mt][3] = __float_as_uint(pa[(r + 8) * SKW + kb + 4]);
            }
            uint32_t bf[8][2];
            #pragma unroll
            for (int nt = 0; nt < 8; nt++) {
                int n = wn + nt * 8 + gid;
                bf[nt][0] = __float_as_uint(pb[n * SKW + kb]);
                bf[nt][1] = __float_as_uint(pb[n * SKW + kb + 4]);
            }
            #pragma unroll
            for (int mt = 0; mt < 4; mt++)
                #pragma unroll
                for (int nt = 0; nt < 8; nt++)
                    mma_tf32(acc[mt][nt], af[mt], bf[nt]);
        }
        __syncthreads();
    }

    #pragma unroll
    for (int mt = 0; mt < 4; mt++) {
        int r0 = rowBase + wm + mt * 16 + gid;
        #pragma unroll
        for (int nt = 0; nt < 8; nt++) {
            int col = colBase + wn + nt * 8 + tig * 2;
            float2 b2 = *(const float2*)(bias + col);
            float2 o0, o1;
            o0.x = acc[mt][nt][0] + b2.x; o0.y = acc[mt][nt][1] + b2.y;
            o1.x = acc[mt][nt][2] + b2.x; o1.y = acc[mt][nt][3] + b2.y;
            if (RESID) {
                float2 r0v = *(const float2*)(resid + (size_t)r0 * ldc + col);
                float2 r1v = *(const float2*)(resid + (size_t)(r0 + 8) * ldc + col);
                o0.x += r0v.x; o0.y += r0v.y;
                o1.x += r1v.x; o1.y += r1v.y;
            }
            if (ROUND) {
                o0.x = to_tf32(o0.x); o0.y = to_tf32(o0.y);
                o1.x = to_tf32(o1.x); o1.y = to_tf32(o1.y);
            }
            *(float2*)(C + (size_t)r0 * ldc + col)       = o0;
            *(float2*)(C + (size_t)(r0 + 8) * ldc + col) = o1;
        }
    }
}

// ---------------------------------------------------------------------------
// Tensor-core flash attention (tf32 mma.sync).
// 128 q-rows/CTA, 64 keys/tile, 4 warps x 32 q-rows. grid (16, 16, 2).
// Fragment layout (m16n8k8, verified by the passing GEMM):
//   A: a0=A[g][t] a1=A[g+8][t] a2=A[g][t+4] a3=A[g+8][t+4]
//   B: b0=B[t][g] b1=B[t+4][g]           (g=lane>>2, t=lane&3)
//   C: c0=C[g][2t] c1=C[g][2t+1] c2=C[g+8][2t] c3=C[g+8][2t+1]
// ---------------------------------------------------------------------------
#define ASTR 68   // smem row stride: (4*gid + tig) mod 32 distinct -> conflict-free

__global__ void __launch_bounds__(128) attn_mma(const float* __restrict__ mask)
{
    extern __shared__ float sm[];
    float* Qs  = sm;                     // 128 x 68
    float* Ks  = Qs + 128 * ASTR;        // 64 x 68
    float* Vs  = Ks + 64 * ASTR;         // 64 x 68
    float* Msk = Vs + 64 * ASTR;         // 64

    int t = threadIdx.x;
    int lane = t & 31, wid = t >> 5;
    int gid = lane >> 2, tig = lane & 3;
    int b = blockIdx.z, h = blockIdx.y, qt = blockIdx.x;
    int qrow0 = b * SS + qt * 128;
    int qr = wid * 32;

    const float* qbase = g_qkv + (size_t)qrow0 * 3 * DD + h * HD;
    #pragma unroll
    for (int i = 0; i < 16; i++) {
        int idx = t + i * 128;
        int r = idx >> 4, d4 = idx & 15;
        *(float4*)(Qs + r * ASTR + d4 * 4) =
            *(const float4*)(qbase + (size_t)r * 3 * DD + d4 * 4);
    }

    float oacc[2][8][4];
    #pragma unroll
    for (int mt = 0; mt < 2; mt++)
        #pragma unroll
        for (int nd = 0; nd < 8; nd++)
            #pragma unroll
            for (int r = 0; r < 4; r++) oacc[mt][nd][r] = 0.f;
    float mrow[2][2] = {{-1e30f, -1e30f}, {-1e30f, -1e30f}};
    float lrow[2][2] = {{0.f, 0.f}, {0.f, 0.f}};

    for (int kt = 0; kt < SS / 64; kt++) {
        __syncthreads();
        const float* kbg = g_qkv + (size_t)(b * SS + kt * 64) * 3 * DD + DD + h * HD;
        const float* vbg = kbg + DD;
        #pragma unroll
        for (int i = 0; i < 8; i++) {
            int idx = t + i * 128;
            int r = idx >> 4, d4 = idx & 15;
            *(float4*)(Ks + r * ASTR + d4 * 4) =
                *(const float4*)(kbg + (size_t)r * 3 * DD + d4 * 4);
            *(float4*)(Vs + r * ASTR + d4 * 4) =
                *(const float4*)(vbg + (size_t)r * 3 * DD + d4 * 4);
        }
        if (t < 64) Msk[t] = mask[b * SS + kt * 64 + t];
        __syncthreads();

        // ---- S = Q K^T ----
        float sacc[2][8][4];
        #pragma unroll
        for (int mt = 0; mt < 2; mt++)
            #pragma unroll
            for (int nt = 0; nt < 8; nt++)
                #pragma unroll
                for (int r = 0; r < 4; r++) sacc[mt][nt][r] = 0.f;

        #pragma unroll
        for (int ks = 0; ks < 8; ks++) {
            uint32_t qa[2][4];
            #pragma unroll
            for (int mt = 0; mt < 2; mt++) {
                const float* qp = Qs + (qr + mt * 16 + gid) * ASTR + ks * 8 + tig;
                qa[mt][0] = __float_as_uint(qp[0]);
                qa[mt][1] = __float_as_uint(qp[8 * ASTR]);
                qa[mt][2] = __float_as_uint(qp[4]);
                qa[mt][3] = __float_as_uint(qp[8 * ASTR + 4]);
            }
            #pragma unroll
            for (int nt = 0; nt < 8; nt++) {
                const float* kp = Ks + (nt * 8 + gid) * ASTR + ks * 8 + tig;
                uint32_t kbf[2] = {__float_as_uint(kp[0]), __float_as_uint(kp[4])};
                mma_tf32(sacc[0][nt], qa[0], kbf);
                mma_tf32(sacc[1][nt], qa[1], kbf);
            }
        }

        // ---- online softmax on C-fragment layout ----
        #pragma unroll
        for (int mt = 0; mt < 2; mt++) {
            float mx0 = mrow[mt][0], mx1 = mrow[mt][1];
            #pragma unroll
            for (int nt = 0; nt < 8; nt++) {
                float mk0 = Msk[nt * 8 + 2 * tig];
                float mk1 = Msk[nt * 8 + 2 * tig + 1];
                float* s = sacc[mt][nt];
                s[0] = s[0] * 0.125f + mk0;
                s[1] = s[1] * 0.125f + mk1;
                s[2] = s[2] * 0.125f + mk0;
                s[3] = s[3] * 0.125f + mk1;
                mx0 = fmaxf(mx0, fmaxf(s[0], s[1]));
                mx1 = fmaxf(mx1, fmaxf(s[2], s[3]));
            }
            mx0 = fmaxf(mx0, __shfl_xor_sync(0xffffffffu, mx0, 1));
            mx0 = fmaxf(mx0, __shfl_xor_sync(0xffffffffu, mx0, 2));
            mx1 = fmaxf(mx1, __shfl_xor_sync(0xffffffffu, mx1, 1));
            mx1 = fmaxf(mx1, __shfl_xor_sync(0xffffffffu, mx1, 2));
            float c0 = __expf(mrow[mt][0] - mx0);
            float c1 = __expf(mrow[mt][1] - mx1);
            mrow[mt][0] = mx0; mrow[mt][1] = mx1;
            float ls0 = 0.f, ls1 = 0.f;
            #pragma unroll
            for (int nt = 0; nt < 8; nt++) {
                float* s = sacc[mt][nt];
                s[0] = __expf(s[0] - mx0);
                s[1] = __expf(s[1] - mx0);
                s[2] = __expf(s[2] - mx1);
                s[3] = __expf(s[3] - mx1);
                ls0 += s[0] + s[1];
                ls1 += s[2] + s[3];
                s[0] = to_tf32(s[0]); s[1] = to_tf32(s[1]);
                s[2] = to_tf32(s[2]); s[3] = to_tf32(s[3]);
            }
            ls0 += __shfl_xor_sync(0xffffffffu, ls0, 1);
            ls0 += __shfl_xor_sync(0xffffffffu, ls0, 2);
            ls1 += __shfl_xor_sync(0xffffffffu, ls1, 1);
            ls1 += __shfl_xor_sync(0xffffffffu, ls1, 2);
            lrow[mt][0] = lrow[mt][0] * c0 + ls0;
            lrow[mt][1] = lrow[mt][1] * c1 + ls1;
            #pragma unroll
            for (int nd = 0; nd < 8; nd++) {
                float* o = oacc[mt][nd];
                o[0] *= c0; o[1] *= c0; o[2] *= c1; o[3] *= c1;
            }
        }

        // ---- O += P V  (P: C-layout -> A-layout via 4-lane shuffles) ----
        int srcA = (lane & ~3) | (tig >> 1);
        int srcB = srcA + 2;
        #pragma unroll
        for (int j = 0; j < 8; j++) {
            uint32_t vbf[8][2];
            #pragma unroll
            for (int nd = 0; nd < 8; nd++) {
                const float* vp = Vs + (j * 8 + tig) * ASTR + nd * 8 + gid;
                vbf[nd][0] = __float_as_uint(vp[0]);
                vbf[nd][1] = __float_as_uint(vp[4 * ASTR]);
            }
            #pragma unroll
            for (int mt = 0; mt < 2; mt++) {
                float* s = sacc[mt][j];
                float v00 = __shfl_sync(0xffffffffu, s[0], srcA);
                float v01 = __shfl_sync(0xffffffffu, s[1], srcA);
                float v10 = __shfl_sync(0xffffffffu, s[2], srcA);
                float v11 = __shfl_sync(0xffffffffu, s[3], srcA);
                float w00 = __shfl_sync(0xffffffffu, s[0], srcB);
                float w01 = __shfl_sync(0xffffffffu, s[1], srcB);
                float w10 = __shfl_sync(0xffffffffu, s[2], srcB);
                float w11 = __shfl_sync(0xffffffffu, s[3], srcB);
                uint32_t pa[4];
                pa[0] = __float_as_uint((tig & 1) ? v01 : v00);
                pa[1] = __float_as_uint((tig & 1) ? v11 : v10);
                pa[2] = __float_as_uint((tig & 1) ? w01 : w00);
                pa[3] = __float_as_uint((tig & 1) ? w11 : w10);
                #pragma unroll
                for (int nd = 0; nd < 8; nd++)
                    mma_tf32(oacc[mt][nd], pa, vbf[nd]);
            }
        }
    }

    // ---- epilogue: normalize, round to tf32 (feeds O-proj), store ctx ----
    #pragma unroll
    for (int mt = 0; mt < 2; mt++) {
        float inv0 = 1.f / lrow[mt][0];
        float inv1 = 1.f / lrow[mt][1];
        int r0 = qrow0 + qr + mt * 16 + gid;
        #pragma unroll
        for (int nd = 0; nd < 8; nd++) {
            int col = h * HD + nd * 8 + 2 * tig;
            float2 lo, hi;
            lo.x = to_tf32(oacc[mt][nd][0] * inv0);
            lo.y = to_tf32(oacc[mt][nd][1] * inv0);
            hi.x = to_tf32(oacc[mt][nd][2] * inv1);
            hi.y = to_tf32(oacc[mt][nd][3] * inv1);
            *(float2*)(g_ctx + (size_t)r0 * DD + col)       = lo;
            *(float2*)(g_ctx + (size_t)(r0 + 8) * DD + col) = hi;
        }
    }
}

// ---------------------------------------------------------------------------
// Launcher
// ---------------------------------------------------------------------------
extern "C" void kernel_launch(void* const* d_in, const int* in_sizes, int n_in,
                              void* d_out, int out_size)
{
    const float* hidden = (const float*)d_in[0];
    const float* mask   = (const float*)d_in[1];
    const float* gamma  = (const float*)d_in[2];
    const float* beta   = (const float*)d_in[3];
    const float* wq = (const float*)d_in[4];
    const float* bq = (const float*)d_in[5];
    const float* wk = (const float*)d_in[6];
    const float* bk = (const float*)d_in[7];
    const float* wv = (const float*)d_in[8];
    const float* bv = (const float*)d_in[9];
    const float* wo = (const float*)d_in[10];
    const float* bo = (const float*)d_in[11];
    float* out = (float*)d_out;

    void *p_xn, *p_qkv, *p_ctx, *p_wr, *p_bqkv;
    cudaGetSymbolAddress(&p_xn,  g_xn);
    cudaGetSymbolAddress(&p_qkv, g_qkv);
    cudaGetSymbolAddress(&p_ctx, g_ctx);
    cudaGetSymbolAddress(&p_wr,  g_wr);
    cudaGetSymbolAddress(&p_bqkv, g_bqkv);
    float* xn   = (float*)p_xn;
    float* qkv  = (float*)p_qkv;
    float* ctx  = (float*)p_ctx;
    float* wr   = (float*)p_wr;
    float* bqkv = (float*)p_bqkv;

    // 0. Prep: tf32-round weights, concat qkv bias
    wprep_kernel<<<4 * DD * DD / 4 / 256, 256>>>(wq, wk, wv, wo, wr);
    bprep_kernel<<<3 * DD / 256, 256>>>(bq, bk, bv, bqkv);

    // 1. LayerNorm (tf32-rounded output)
    ln_kernel<<<ROWS, 256>>>(hidden, gamma, beta, xn);

    // 2. Fused QKV projection: [4096,1024] @ [3072,1024]^T
    gemm_mma<false, true><<<dim3(3 * DD / 128, ROWS / 128), 128>>>(
        xn, wr, bqkv, nullptr, qkv, DD, 3 * DD);

    // 3. Tensor-core flash attention
    int smem = (128 * ASTR + 64 * ASTR * 2 + 64) * sizeof(float);
    cudaFuncSetAttribute(attn_mma, cudaFuncAttributeMaxDynamicSharedMemorySize, smem);
    attn_mma<<<dim3(SS / 128, HH, BB), 128, smem>>>(mask);

    // 4. Output projection + bias + residual
    gemm_mma<true, false><<<dim3(DD / 128, ROWS / 128), 128>>>(
        ctx, wr + 3 * DD * DD, bo, hidden, out, DD, DD);
}

// round 6
// speedup vs baseline: 5.0563x; 1.0952x over previous
#include <cuda_runtime.h>
#include <cstdint>
#include <math.h>

#define BB 2
#define SS 2048
#define DD 1024
#define HH 16
#define HD 64
#define ROWS (BB*SS)

// Scratch (static device globals — no runtime allocation)
__device__ float g_xn[ROWS * DD];
__device__ float g_qkv[ROWS * 3 * DD];
__device__ float g_ctx[ROWS * DD];
__device__ float g_wr[4 * DD * DD];   // tf32-rounded wq,wk,wv,wo
__device__ float g_bqkv[3 * DD];

// ---------------------------------------------------------------------------
// helpers
// ---------------------------------------------------------------------------
__device__ __forceinline__ uint32_t smem_u32(const void* p) {
    uint32_t a;
    asm("{ .reg .u64 t; cvta.to.shared.u64 t, %1; cvt.u32.u64 %0, t; }"
        : "=r"(a) : "l"(p));
    return a;
}

__device__ __forceinline__ float to_tf32(float x) {
    uint32_t u;
    asm("cvt.rna.tf32.f32 %0, %1;" : "=r"(u) : "f"(x));
    return __uint_as_float(u);
}

#define CP_ASYNC16(smem_addr, gptr) \
    asm volatile("cp.async.cg.shared.global [%0], [%1], 16;" \
                 :: "r"(smem_addr), "l"(gptr) : "memory")
#define CP_COMMIT() asm volatile("cp.async.commit_group;" ::: "memory")
#define CP_WAIT(N)  asm volatile("cp.async.wait_group %0;" :: "n"(N) : "memory")

__device__ __forceinline__ void mma_tf32(float* c, const uint32_t* a, const uint32_t* b) {
    asm volatile(
        "mma.sync.aligned.m16n8k8.row.col.f32.tf32.tf32.f32 "
        "{%0,%1,%2,%3}, {%4,%5,%6,%7}, {%8,%9}, {%0,%1,%2,%3};"
        : "+f"(c[0]), "+f"(c[1]), "+f"(c[2]), "+f"(c[3])
        : "r"(a[0]), "r"(a[1]), "r"(a[2]), "r"(a[3]), "r"(b[0]), "r"(b[1]));
}

// ---------------------------------------------------------------------------
// Weight prep: round all 4 weight matrices to tf32 (rna)
// ---------------------------------------------------------------------------
__global__ void __launch_bounds__(256) wprep_kernel(
    const float* __restrict__ wq, const float* __restrict__ wk,
    const float* __restrict__ wv, const float* __restrict__ wo,
    float* __restrict__ dst)
{
    int i = blockIdx.x * 256 + threadIdx.x;        // float4 index
    const float* srcs[4] = {wq, wk, wv, wo};
    int which = i / (DD * DD / 4);
    int off   = i % (DD * DD / 4);
    float4 v = ((const float4*)srcs[which])[off];
    v.x = to_tf32(v.x); v.y = to_tf32(v.y);
    v.z = to_tf32(v.z); v.w = to_tf32(v.w);
    ((float4*)dst)[i] = v;
}

__global__ void __launch_bounds__(256) bprep_kernel(
    const float* __restrict__ bq, const float* __restrict__ bk,
    const float* __restrict__ bv, float* __restrict__ dst)
{
    int i = blockIdx.x * 256 + threadIdx.x;        // 0..3071
    const float* s = (i < DD) ? bq : ((i < 2 * DD) ? bk : bv);
    dst[i] = s[i & (DD - 1)];
}

// ---------------------------------------------------------------------------
// LayerNorm: one block per row; output rounded to tf32
// ---------------------------------------------------------------------------
__global__ void __launch_bounds__(256) ln_kernel(
    const float* __restrict__ x, const float* __restrict__ gamma,
    const float* __restrict__ beta, float* __restrict__ out)
{
    int row = blockIdx.x;
    int t = threadIdx.x;
    float4 v = ((const float4*)(x + (size_t)row * DD))[t];
    float s  = v.x + v.y + v.z + v.w;
    float ss = v.x*v.x + v.y*v.y + v.z*v.z + v.w*v.w;

    #pragma unroll
    for (int o = 16; o; o >>= 1) {
        s  += __shfl_xor_sync(0xffffffffu, s,  o);
        ss += __shfl_xor_sync(0xffffffffu, ss, o);
    }
    __shared__ float rs[8], rss[8];
    int w = t >> 5;
    if ((t & 31) == 0) { rs[w] = s; rss[w] = ss; }
    __syncthreads();
    if (t < 32) {
        float a  = (t < 8) ? rs[t]  : 0.f;
        float aa = (t < 8) ? rss[t] : 0.f;
        #pragma unroll
        for (int o = 4; o; o >>= 1) {
            a  += __shfl_xor_sync(0xffffffffu, a,  o);
            aa += __shfl_xor_sync(0xffffffffu, aa, o);
        }
        if (t == 0) { rs[0] = a; rss[0] = aa; }
    }
    __syncthreads();
    float mean = rs[0] * (1.0f / DD);
    float var  = rss[0] * (1.0f / DD) - mean * mean;
    float rstd = rsqrtf(var + 1e-12f);

    float4 g  = ((const float4*)gamma)[t];
    float4 bt = ((const float4*)beta)[t];
    float4 r;
    r.x = to_tf32((v.x - mean) * rstd * g.x + bt.x);
    r.y = to_tf32((v.y - mean) * rstd * g.y + bt.y);
    r.z = to_tf32((v.z - mean) * rstd * g.z + bt.z);
    r.w = to_tf32((v.w - mean) * rstd * g.w + bt.w);
    ((float4*)(out + (size_t)row * DD))[t] = r;
}

// ---------------------------------------------------------------------------
// mma.sync tf32 GEMM-NT: C[M,·] = A[M,K] @ W[N,K]^T + bias (+ residual)
// Block tile 128x256, 256 threads = 8 warps (2x4), warp tile 64x64.
// BK=16, 3-stage cp.async pipeline (empty-commit tail). DYNAMIC smem (90KB).
// ---------------------------------------------------------------------------
#define SKW 20
#define GSTG 3
#define GA_STAGE (128 * SKW)
#define GB_STAGE (256 * SKW)
#define GSMEM_FLOATS (GSTG * (GA_STAGE + GB_STAGE))

template<bool RESID, bool ROUND>
__global__ void __launch_bounds__(256) gemm_mma(
    const float* __restrict__ A, const float* __restrict__ W,
    const float* __restrict__ bias, const float* __restrict__ resid,
    float* __restrict__ C, int lda, int ldc)
{
    extern __shared__ __align__(16) float gsm[];
    float* sAb = gsm;                       // GSTG stages of 128*SKW
    float* sBb = gsm + GSTG * GA_STAGE;     // GSTG stages of 256*SKW

    int tid  = threadIdx.x;
    int lane = tid & 31;
    int wid  = tid >> 5;
    int wm = (wid & 1) * 64;
    int wn = (wid >> 1) * 64;
    int rowBase = blockIdx.y * 128;
    int colBase = blockIdx.x * 256;
    int gid = lane >> 2;
    int tig = lane & 3;

    int lrow = tid >> 2;          // 0..63
    int lc4  = tid & 3;           // 0..3
    const float* gA0 = A + (size_t)(rowBase + lrow) * lda + lc4 * 4;
    const float* gA1 = gA0 + (size_t)64 * lda;
    const float* gB0 = W + (size_t)(colBase + lrow) * DD + lc4 * 4;
    const float* gB1 = gB0 + (size_t)64 * DD;
    const float* gB2 = gB0 + (size_t)128 * DD;
    const float* gB3 = gB0 + (size_t)192 * DD;

    uint32_t offR0 = (uint32_t)((lrow * SKW + lc4 * 4) * 4);
    uint32_t offR1 = (uint32_t)(((lrow + 64) * SKW + lc4 * 4) * 4);

    uint32_t sawA[GSTG], sawB[GSTG];
    #pragma unroll
    for (int s = 0; s < GSTG; s++) {
        sawA[s] = smem_u32(sAb + s * GA_STAGE);
        sawB[s] = smem_u32(sBb + s * GB_STAGE);
    }

    float acc[4][8][4];
    #pragma unroll
    for (int mt = 0; mt < 4; mt++)
        #pragma unroll
        for (int nt = 0; nt < 8; nt++)
            #pragma unroll
            for (int r = 0; r < 4; r++) acc[mt][nt][r] = 0.f;

    const int NCHUNK = DD / 16;   // 64

    // prefetch chunks 0,1
    #pragma unroll
    for (int p = 0; p < 2; p++) {
        int k0 = p * 16;
        CP_ASYNC16(sawA[p] + offR0, gA0 + k0);
        CP_ASYNC16(sawA[p] + offR1, gA1 + k0);
        CP_ASYNC16(sawB[p] + offR0, gB0 + k0);
        CP_ASYNC16(sawB[p] + offR1, gB1 + k0);
        CP_ASYNC16(sawB[p] + offR0 + 128 * SKW * 4, gB2 + k0);
        CP_ASYNC16(sawB[p] + offR1 + 128 * SKW * 4, gB3 + k0);
        CP_COMMIT();
    }

    for (int c = 0; c < NCHUNK; c++) {
        if (c + 2 < NCHUNK) {
            int s = (c + 2) % GSTG;
            int k0 = (c + 2) * 16;
            CP_ASYNC16(sawA[s] + offR0, gA0 + k0);
            CP_ASYNC16(sawA[s] + offR1, gA1 + k0);
            CP_ASYNC16(sawB[s] + offR0, gB0 + k0);
            CP_ASYNC16(sawB[s] + offR1, gB1 + k0);
            CP_ASYNC16(sawB[s] + offR0 + 128 * SKW * 4, gB2 + k0);
            CP_ASYNC16(sawB[s] + offR1 + 128 * SKW * 4, gB3 + k0);
        }
        CP_COMMIT();              // (possibly empty) keeps group counting aligned
        CP_WAIT(2);
        __syncthreads();

        const float* pa = sAb + (c % GSTG) * GA_STAGE;
        const float* pb = sBb + (c % GSTG) * GB_STAGE;
        #pragma unroll
        for (int ks = 0; ks < 2; ks++) {
            int kb = ks * 8 + tig;
            uint32_t af[4][4];
            #pragma unroll
            for (int mt = 0; mt < 4; mt++) {
                int r = wm + mt * 16 + gid;
                af[mt][0] = __float_as_uint(pa[r * SKW + kb]);
                af[mt][1] = __float_as_uint(pa[(r + 8) * SKW + kb]);
                af[mt][2] = __float_as_uint(pa[r * SKW + kb + 4]);
                af[mt][3] = __float_as_uint(pa[(r + 8) * SKW + kb + 4]);
            }
            uint32_t bf[8][2];
            #pragma unroll
            for (int nt = 0; nt < 8; nt++) {
                int n = wn + nt * 8 + gid;
                bf[nt][0] = __float_as_uint(pb[n * SKW + kb]);
                bf[nt][1] = __float_as_uint(pb[n * SKW + kb + 4]);
            }
            #pragma unroll
            for (int mt = 0; mt < 4; mt++)
                #pragma unroll
                for (int nt = 0; nt < 8; nt++)
                    mma_tf32(acc[mt][nt], af[mt], bf[nt]);
        }
        __syncthreads();
    }

    #pragma unroll
    for (int mt = 0; mt < 4; mt++) {
        int r0 = rowBase + wm + mt * 16 + gid;
        #pragma unroll
        for (int nt = 0; nt < 8; nt++) {
            int col = colBase + wn + nt * 8 + tig * 2;
            float2 b2 = *(const float2*)(bias + col);
            float2 o0, o1;
            o0.x = acc[mt][nt][0] + b2.x; o0.y = acc[mt][nt][1] + b2.y;
            o1.x = acc[mt][nt][2] + b2.x; o1.y = acc[mt][nt][3] + b2.y;
            if (RESID) {
                float2 r0v = *(const float2*)(resid + (size_t)r0 * ldc + col);
                float2 r1v = *(const float2*)(resid + (size_t)(r0 + 8) * ldc + col);
                o0.x += r0v.x; o0.y += r0v.y;
                o1.x += r1v.x; o1.y += r1v.y;
            }
            if (ROUND) {
                o0.x = to_tf32(o0.x); o0.y = to_tf32(o0.y);
                o1.x = to_tf32(o1.x); o1.y = to_tf32(o1.y);
            }
            *(float2*)(C + (size_t)r0 * ldc + col)       = o0;
            *(float2*)(C + (size_t)(r0 + 8) * ldc + col) = o1;
        }
    }
}

// ---------------------------------------------------------------------------
// Tensor-core flash attention (tf32 mma.sync).
// 128 q-rows/CTA, 64 keys/tile, 256 threads = 8 warps x 16 q-rows.
// grid (16, 16, 2). ~110 regs -> 2 CTAs/SM = 16 warps/SM.
// ---------------------------------------------------------------------------
#define ASTR 68

__global__ void __launch_bounds__(256) attn_mma(const float* __restrict__ mask)
{
    extern __shared__ float sm[];
    float* Qs  = sm;                     // 128 x 68
    float* Ks  = Qs + 128 * ASTR;        // 64 x 68
    float* Vs  = Ks + 64 * ASTR;         // 64 x 68
    float* Msk = Vs + 64 * ASTR;         // 64

    int t = threadIdx.x;
    int lane = t & 31, wid = t >> 5;
    int gid = lane >> 2, tig = lane & 3;
    int b = blockIdx.z, h = blockIdx.y, qt = blockIdx.x;
    int qrow0 = b * SS + qt * 128;
    int qr = wid * 16;

    const float* qbase = g_qkv + (size_t)qrow0 * 3 * DD + h * HD;
    #pragma unroll
    for (int i = 0; i < 8; i++) {
        int idx = t + i * 256;
        int r = idx >> 4, d4 = idx & 15;
        *(float4*)(Qs + r * ASTR + d4 * 4) =
            *(const float4*)(qbase + (size_t)r * 3 * DD + d4 * 4);
    }

    float oacc[8][4];
    #pragma unroll
    for (int nd = 0; nd < 8; nd++)
        #pragma unroll
        for (int r = 0; r < 4; r++) oacc[nd][r] = 0.f;
    float mrow[2] = {-1e30f, -1e30f};
    float lrow[2] = {0.f, 0.f};

    for (int kt = 0; kt < SS / 64; kt++) {
        __syncthreads();
        const float* kbg = g_qkv + (size_t)(b * SS + kt * 64) * 3 * DD + DD + h * HD;
        const float* vbg = kbg + DD;
        #pragma unroll
        for (int i = 0; i < 4; i++) {
            int idx = t + i * 256;
            int r = idx >> 4, d4 = idx & 15;
            *(float4*)(Ks + r * ASTR + d4 * 4) =
                *(const float4*)(kbg + (size_t)r * 3 * DD + d4 * 4);
            *(float4*)(Vs + r * ASTR + d4 * 4) =
                *(const float4*)(vbg + (size_t)r * 3 * DD + d4 * 4);
        }
        if (t < 64) Msk[t] = mask[b * SS + kt * 64 + t];
        __syncthreads();

        // ---- S = Q K^T ----
        float sacc[8][4];
        #pragma unroll
        for (int nt = 0; nt < 8; nt++)
            #pragma unroll
            for (int r = 0; r < 4; r++) sacc[nt][r] = 0.f;

        #pragma unroll
        for (int ks = 0; ks < 8; ks++) {
            uint32_t qa[4];
            const float* qp = Qs + (qr + gid) * ASTR + ks * 8 + tig;
            qa[0] = __float_as_uint(qp[0]);
            qa[1] = __float_as_uint(qp[8 * ASTR]);
            qa[2] = __float_as_uint(qp[4]);
            qa[3] = __float_as_uint(qp[8 * ASTR + 4]);
            #pragma unroll
            for (int nt = 0; nt < 8; nt++) {
                const float* kp = Ks + (nt * 8 + gid) * ASTR + ks * 8 + tig;
                uint32_t kbf[2] = {__float_as_uint(kp[0]), __float_as_uint(kp[4])};
                mma_tf32(sacc[nt], qa, kbf);
            }
        }

        // ---- online softmax on C-fragment layout ----
        {
            float mx0 = mrow[0], mx1 = mrow[1];
            #pragma unroll
            for (int nt = 0; nt < 8; nt++) {
                float mk0 = Msk[nt * 8 + 2 * tig];
                float mk1 = Msk[nt * 8 + 2 * tig + 1];
                float* s = sacc[nt];
                s[0] = s[0] * 0.125f + mk0;
                s[1] = s[1] * 0.125f + mk1;
                s[2] = s[2] * 0.125f + mk0;
                s[3] = s[3] * 0.125f + mk1;
                mx0 = fmaxf(mx0, fmaxf(s[0], s[1]));
                mx1 = fmaxf(mx1, fmaxf(s[2], s[3]));
            }
            mx0 = fmaxf(mx0, __shfl_xor_sync(0xffffffffu, mx0, 1));
            mx0 = fmaxf(mx0, __shfl_xor_sync(0xffffffffu, mx0, 2));
            mx1 = fmaxf(mx1, __shfl_xor_sync(0xffffffffu, mx1, 1));
            mx1 = fmaxf(mx1, __shfl_xor_sync(0xffffffffu, mx1, 2));
            float c0 = __expf(mrow[0] - mx0);
            float c1 = __expf(mrow[1] - mx1);
            mrow[0] = mx0; mrow[1] = mx1;
            float ls0 = 0.f, ls1 = 0.f;
            #pragma unroll
            for (int nt = 0; nt < 8; nt++) {
                float* s = sacc[nt];
                s[0] = __expf(s[0] - mx0);
                s[1] = __expf(s[1] - mx0);
                s[2] = __expf(s[2] - mx1);
                s[3] = __expf(s[3] - mx1);
                ls0 += s[0] + s[1];
                ls1 += s[2] + s[3];
                s[0] = to_tf32(s[0]); s[1] = to_tf32(s[1]);
                s[2] = to_tf32(s[2]); s[3] = to_tf32(s[3]);
            }
            ls0 += __shfl_xor_sync(0xffffffffu, ls0, 1);
            ls0 += __shfl_xor_sync(0xffffffffu, ls0, 2);
            ls1 += __shfl_xor_sync(0xffffffffu, ls1, 1);
            ls1 += __shfl_xor_sync(0xffffffffu, ls1, 2);
            lrow[0] = lrow[0] * c0 + ls0;
            lrow[1] = lrow[1] * c1 + ls1;
            #pragma unroll
            for (int nd = 0; nd < 8; nd++) {
                float* o = oacc[nd];
                o[0] *= c0; o[1] *= c0; o[2] *= c1; o[3] *= c1;
            }
        }

        // ---- O += P V  (P: C-layout -> A-layout via 4-lane shuffles) ----
        int srcA = (lane & ~3) | (tig >> 1);
        int srcB = srcA + 2;
        #pragma unroll
        for (int j = 0; j < 8; j++) {
            uint32_t vbf[8][2];
            #pragma unroll
            for (int nd = 0; nd < 8; nd++) {
                const float* vp = Vs + (j * 8 + tig) * ASTR + nd * 8 + gid;
                vbf[nd][0] = __float_as_uint(vp[0]);
                vbf[nd][1] = __float_as_uint(vp[4 * ASTR]);
            }
            float* s = sacc[j];
            float v00 = __shfl_sync(0xffffffffu, s[0], srcA);
            float v01 = __shfl_sync(0xffffffffu, s[1], srcA);
            float v10 = __shfl_sync(0xffffffffu, s[2], srcA);
            float v11 = __shfl_sync(0xffffffffu, s[3], srcA);
            float w00 = __shfl_sync(0xffffffffu, s[0], srcB);
            float w01 = __shfl_sync(0xffffffffu, s[1], srcB);
            float w10 = __shfl_sync(0xffffffffu, s[2], srcB);
            float w11 = __shfl_sync(0xffffffffu, s[3], srcB);
            uint32_t pa[4];
            pa[0] = __float_as_uint((tig & 1) ? v01 : v00);
            pa[1] = __float_as_uint((tig & 1) ? v11 : v10);
            pa[2] = __float_as_uint((tig & 1) ? w01 : w00);
            pa[3] = __float_as_uint((tig & 1) ? w11 : w10);
            #pragma unroll
            for (int nd = 0; nd < 8; nd++)
                mma_tf32(oacc[nd], pa, vbf[nd]);
        }
    }

    // ---- epilogue: normalize, round to tf32 (feeds O-proj), store ctx ----
    {
        float inv0 = 1.f / lrow[0];
        float inv1 = 1.f / lrow[1];
        int r0 = qrow0 + qr + gid;
        #pragma unroll
        for (int nd = 0; nd < 8; nd++) {
            int col = h * HD + nd * 8 + 2 * tig;
            float2 lo, hi;
            lo.x = to_tf32(oacc[nd][0] * inv0);
            lo.y = to_tf32(oacc[nd][1] * inv0);
            hi.x = to_tf32(oacc[nd][2] * inv1);
            hi.y = to_tf32(oacc[nd][3] * inv1);
            *(float2*)(g_ctx + (size_t)r0 * DD + col)       = lo;
            *(float2*)(g_ctx + (size_t)(r0 + 8) * DD + col) = hi;
        }
    }
}

// ---------------------------------------------------------------------------
// Launcher
// ---------------------------------------------------------------------------
extern "C" void kernel_launch(void* const* d_in, const int* in_sizes, int n_in,
                              void* d_out, int out_size)
{
    const float* hidden = (const float*)d_in[0];
    const float* mask   = (const float*)d_in[1];
    const float* gamma  = (const float*)d_in[2];
    const float* beta   = (const float*)d_in[3];
    const float* wq = (const float*)d_in[4];
    const float* bq = (const float*)d_in[5];
    const float* wk = (const float*)d_in[6];
    const float* bk = (const float*)d_in[7];
    const float* wv = (const float*)d_in[8];
    const float* bv = (const float*)d_in[9];
    const float* wo = (const float*)d_in[10];
    const float* bo = (const float*)d_in[11];
    float* out = (float*)d_out;

    void *p_xn, *p_qkv, *p_ctx, *p_wr, *p_bqkv;
    cudaGetSymbolAddress(&p_xn,  g_xn);
    cudaGetSymbolAddress(&p_qkv, g_qkv);
    cudaGetSymbolAddress(&p_ctx, g_ctx);
    cudaGetSymbolAddress(&p_wr,  g_wr);
    cudaGetSymbolAddress(&p_bqkv, g_bqkv);
    float* xn   = (float*)p_xn;
    float* qkv  = (float*)p_qkv;
    float* ctx  = (float*)p_ctx;
    float* wr   = (float*)p_wr;
    float* bqkv = (float*)p_bqkv;

    // 0. Prep: tf32-round weights, concat qkv bias
    wprep_kernel<<<4 * DD * DD / 4 / 256, 256>>>(wq, wk, wv, wo, wr);
    bprep_kernel<<<3 * DD / 256, 256>>>(bq, bk, bv, bqkv);

    // 1. LayerNorm (tf32-rounded output)
    ln_kernel<<<ROWS, 256>>>(hidden, gamma, beta, xn);

    // 2. Fused QKV projection: [4096,1024] @ [3072,1024]^T
    int gsmem = GSMEM_FLOATS * (int)sizeof(float);   // 92160 B
    cudaFuncSetAttribute(gemm_mma<false, true>,
                         cudaFuncAttributeMaxDynamicSharedMemorySize, gsmem);
    cudaFuncSetAttribute(gemm_mma<true, false>,
                         cudaFuncAttributeMaxDynamicSharedMemorySize, gsmem);
    gemm_mma<false, true><<<dim3(3 * DD / 256, ROWS / 128), 256, gsmem>>>(
        xn, wr, bqkv, nullptr, qkv, DD, 3 * DD);

    // 3. Tensor-core flash attention
    int smem = (128 * ASTR + 64 * ASTR * 2 + 64) * sizeof(float);
    cudaFuncSetAttribute(attn_mma, cudaFuncAttributeMaxDynamicSharedMemorySize, smem);
    attn_mma<<<dim3(SS / 128, HH, BB), 256, smem>>>(mask);

    // 4. Output projection + bias + residual
    gemm_mma<true, false><<<dim3(DD / 256, ROWS / 128), 256, gsmem>>>(
        ctx, wr + 3 * DD * DD, bo, hidden, out, DD, DD);
}

// round 9
// speedup vs baseline: 8.1689x; 1.6156x over previous
#include <cuda_runtime.h>
#include <cuda_bf16.h>
#include <cstdint>
#include <math.h>

#define BB 2
#define SS 2048
#define DD 1024
#define HH 16
#define HD 64
#define ROWS (BB*SS)

// Scratch (static device globals — no runtime allocation)
__device__ __nv_bfloat16 g_xn16[ROWS * DD];
__device__ __nv_bfloat16 g_qkv16[ROWS * 3 * DD];
__device__ __nv_bfloat16 g_ctx16[ROWS * DD];
__device__ __nv_bfloat16 g_w16[4 * DD * DD];   // bf16 wq,wk,wv,wo
__device__ float g_bqkv[3 * DD];

// ---------------------------------------------------------------------------
// helpers
// ---------------------------------------------------------------------------
__device__ __forceinline__ uint32_t smem_u32(const void* p) {
    uint32_t a;
    asm("{ .reg .u64 t; cvta.to.shared.u64 t, %1; cvt.u32.u64 %0, t; }"
        : "=r"(a) : "l"(p));
    return a;
}

// pack two fp32 -> bf16x2 (lo = first arg, hi = second), round-to-nearest
__device__ __forceinline__ uint32_t pack_bf16(float lo, float hi) {
    uint32_t d;
    asm("cvt.rn.bf16x2.f32 %0, %1, %2;" : "=r"(d) : "f"(hi), "f"(lo));
    return d;
}

#define CP_ASYNC16(smem_addr, gptr) \
    asm volatile("cp.async.cg.shared.global [%0], [%1], 16;" \
                 :: "r"(smem_addr), "l"(gptr) : "memory")
#define CP_COMMIT() asm volatile("cp.async.commit_group;" ::: "memory")
#define CP_WAIT(N)  asm volatile("cp.async.wait_group %0;" :: "n"(N) : "memory")

__device__ __forceinline__ void mma_bf16(float* c, const uint32_t* a, const uint32_t* b) {
    asm volatile(
        "mma.sync.aligned.m16n8k16.row.col.f32.bf16.bf16.f32 "
        "{%0,%1,%2,%3}, {%4,%5,%6,%7}, {%8,%9}, {%0,%1,%2,%3};"
        : "+f"(c[0]), "+f"(c[1]), "+f"(c[2]), "+f"(c[3])
        : "r"(a[0]), "r"(a[1]), "r"(a[2]), "r"(a[3]), "r"(b[0]), "r"(b[1]));
}

// ---------------------------------------------------------------------------
// Weight prep: fp32 -> bf16 (rn) for all 4 weight matrices
// ---------------------------------------------------------------------------
__global__ void __launch_bounds__(256) wprep_kernel(
    const float* __restrict__ wq, const float* __restrict__ wk,
    const float* __restrict__ wv, const float* __restrict__ wo,
    __nv_bfloat16* __restrict__ dst)
{
    int i = blockIdx.x * 256 + threadIdx.x;        // float4 index
    const float* srcs[4] = {wq, wk, wv, wo};
    int which = i / (DD * DD / 4);
    int off   = i % (DD * DD / 4);
    float4 v = ((const float4*)srcs[which])[off];
    uint2 o;
    o.x = pack_bf16(v.x, v.y);
    o.y = pack_bf16(v.z, v.w);
    ((uint2*)dst)[i] = o;
}

__global__ void __launch_bounds__(256) bprep_kernel(
    const float* __restrict__ bq, const float* __restrict__ bk,
    const float* __restrict__ bv, float* __restrict__ dst)
{
    int i = blockIdx.x * 256 + threadIdx.x;        // 0..3071
    const float* s = (i < DD) ? bq : ((i < 2 * DD) ? bk : bv);
    dst[i] = s[i & (DD - 1)];
}

// ---------------------------------------------------------------------------
// LayerNorm: one block per row; output bf16
// ---------------------------------------------------------------------------
__global__ void __launch_bounds__(256) ln_kernel(
    const float* __restrict__ x, const float* __restrict__ gamma,
    const float* __restrict__ beta, __nv_bfloat16* __restrict__ out)
{
    int row = blockIdx.x;
    int t = threadIdx.x;
    float4 v = ((const float4*)(x + (size_t)row * DD))[t];
    float s  = v.x + v.y + v.z + v.w;
    float ss = v.x*v.x + v.y*v.y + v.z*v.z + v.w*v.w;

    #pragma unroll
    for (int o = 16; o; o >>= 1) {
        s  += __shfl_xor_sync(0xffffffffu, s,  o);
        ss += __shfl_xor_sync(0xffffffffu, ss, o);
    }
    __shared__ float rs[8], rss[8];
    int w = t >> 5;
    if ((t & 31) == 0) { rs[w] = s; rss[w] = ss; }
    __syncthreads();
    if (t < 32) {
        float a  = (t < 8) ? rs[t]  : 0.f;
        float aa = (t < 8) ? rss[t] : 0.f;
        #pragma unroll
        for (int o = 4; o; o >>= 1) {
            a  += __shfl_xor_sync(0xffffffffu, a,  o);
            aa += __shfl_xor_sync(0xffffffffu, aa, o);
        }
        if (t == 0) { rs[0] = a; rss[0] = aa; }
    }
    __syncthreads();
    float mean = rs[0] * (1.0f / DD);
    float var  = rss[0] * (1.0f / DD) - mean * mean;
    float rstd = rsqrtf(var + 1e-12f);

    float4 g  = ((const float4*)gamma)[t];
    float4 bt = ((const float4*)beta)[t];
    uint2 o;
    o.x = pack_bf16((v.x - mean) * rstd * g.x + bt.x,
                    (v.y - mean) * rstd * g.y + bt.y);
    o.y = pack_bf16((v.z - mean) * rstd * g.z + bt.z,
                    (v.w - mean) * rstd * g.w + bt.w);
    ((uint2*)(out + (size_t)row * DD))[t] = o;
}

// ---------------------------------------------------------------------------
// bf16 mma.sync GEMM-NT: C[M,·] = A[M,K] @ W[N,K]^T + bias (+ residual)
// All tile data handled as bf16 PAIRS (uint32). K=1024 elems = 512 pairs.
// Chunk = 16 pairs (32 elems), NCHUNK=32. Block 128x256, 8 warps 64x64.
// 3-stage cp.async pipeline, dynamic smem.
// ---------------------------------------------------------------------------
#define SKW 20
#define GSTG 3
#define GA_STAGE (128 * SKW)
#define GB_STAGE (256 * SKW)
#define GSMEM_BYTES (GSTG * (GA_STAGE + GB_STAGE) * 4)
#define KP (DD / 2)            // 512 pairs per row

template<bool OUT_BF16>
__global__ void __launch_bounds__(256) gemm_mma(
    const uint32_t* __restrict__ A, const uint32_t* __restrict__ W,
    const float* __restrict__ bias, const float* __restrict__ resid,
    void* __restrict__ Cout, int ldc)
{
    extern __shared__ __align__(16) uint32_t gsm[];
    uint32_t* sAb = gsm;
    uint32_t* sBb = gsm + GSTG * GA_STAGE;

    int tid  = threadIdx.x;
    int lane = tid & 31;
    int wid  = tid >> 5;
    int wm = (wid & 1) * 64;
    int wn = (wid >> 1) * 64;
    int rowBase = blockIdx.y * 128;
    int colBase = blockIdx.x * 256;
    int gid = lane >> 2;
    int tig = lane & 3;

    int lrow = tid >> 2;          // 0..63
    int lc4  = tid & 3;           // 0..3 (16B = 4 pairs each)
    const uint32_t* gA0 = A + (size_t)(rowBase + lrow) * KP + lc4 * 4;
    const uint32_t* gA1 = gA0 + (size_t)64 * KP;
    const uint32_t* gB0 = W + (size_t)(colBase + lrow) * KP + lc4 * 4;
    const uint32_t* gB1 = gB0 + (size_t)64 * KP;
    const uint32_t* gB2 = gB0 + (size_t)128 * KP;
    const uint32_t* gB3 = gB0 + (size_t)192 * KP;

    uint32_t offR0 = (uint32_t)((lrow * SKW + lc4 * 4) * 4);
    uint32_t offR1 = (uint32_t)(((lrow + 64) * SKW + lc4 * 4) * 4);

    uint32_t sawA[GSTG], sawB[GSTG];
    #pragma unroll
    for (int s = 0; s < GSTG; s++) {
        sawA[s] = smem_u32(sAb + s * GA_STAGE);
        sawB[s] = smem_u32(sBb + s * GB_STAGE);
    }

    float acc[4][8][4];
    #pragma unroll
    for (int mt = 0; mt < 4; mt++)
        #pragma unroll
        for (int nt = 0; nt < 8; nt++)
            #pragma unroll
            for (int r = 0; r < 4; r++) acc[mt][nt][r] = 0.f;

    const int NCHUNK = KP / 16;   // 32

    #pragma unroll
    for (int p = 0; p < 2; p++) {
        int k0 = p * 16;
        CP_ASYNC16(sawA[p] + offR0, gA0 + k0);
        CP_ASYNC16(sawA[p] + offR1, gA1 + k0);
        CP_ASYNC16(sawB[p] + offR0, gB0 + k0);
        CP_ASYNC16(sawB[p] + offR1, gB1 + k0);
        CP_ASYNC16(sawB[p] + offR0 + 128 * SKW * 4, gB2 + k0);
        CP_ASYNC16(sawB[p] + offR1 + 128 * SKW * 4, gB3 + k0);
        CP_COMMIT();
    }

    for (int c = 0; c < NCHUNK; c++) {
        if (c + 2 < NCHUNK) {
            int s = (c + 2) % GSTG;
            int k0 = (c + 2) * 16;
            CP_ASYNC16(sawA[s] + offR0, gA0 + k0);
            CP_ASYNC16(sawA[s] + offR1, gA1 + k0);
            CP_ASYNC16(sawB[s] + offR0, gB0 + k0);
            CP_ASYNC16(sawB[s] + offR1, gB1 + k0);
            CP_ASYNC16(sawB[s] + offR0 + 128 * SKW * 4, gB2 + k0);
            CP_ASYNC16(sawB[s] + offR1 + 128 * SKW * 4, gB3 + k0);
        }
        CP_COMMIT();
        CP_WAIT(2);
        __syncthreads();

        const uint32_t* pa = sAb + (c % GSTG) * GA_STAGE;
        const uint32_t* pb = sBb + (c % GSTG) * GB_STAGE;
        #pragma unroll
        for (int ks = 0; ks < 2; ks++) {
            int kb = ks * 8 + tig;          // pair index within chunk
            uint32_t af[4][4];
            #pragma unroll
            for (int mt = 0; mt < 4; mt++) {
                int r = wm + mt * 16 + gid;
                af[mt][0] = pa[r * SKW + kb];
                af[mt][1] = pa[(r + 8) * SKW + kb];
                af[mt][2] = pa[r * SKW + kb + 4];
                af[mt][3] = pa[(r + 8) * SKW + kb + 4];
            }
            uint32_t bf[8][2];
            #pragma unroll
            for (int nt = 0; nt < 8; nt++) {
                int n = wn + nt * 8 + gid;
                bf[nt][0] = pb[n * SKW + kb];
                bf[nt][1] = pb[n * SKW + kb + 4];
            }
            #pragma unroll
            for (int mt = 0; mt < 4; mt++)
                #pragma unroll
                for (int nt = 0; nt < 8; nt++)
                    mma_bf16(acc[mt][nt], af[mt], bf[nt]);
        }
        __syncthreads();
    }

    #pragma unroll
    for (int mt = 0; mt < 4; mt++) {
        int r0 = rowBase + wm + mt * 16 + gid;
        #pragma unroll
        for (int nt = 0; nt < 8; nt++) {
            int col = colBase + wn + nt * 8 + tig * 2;
            float2 b2 = *(const float2*)(bias + col);
            float o00 = acc[mt][nt][0] + b2.x, o01 = acc[mt][nt][1] + b2.y;
            float o10 = acc[mt][nt][2] + b2.x, o11 = acc[mt][nt][3] + b2.y;
            if (OUT_BF16) {
                __nv_bfloat16* C16 = (__nv_bfloat16*)Cout;
                *(uint32_t*)(C16 + (size_t)r0 * ldc + col)       = pack_bf16(o00, o01);
                *(uint32_t*)(C16 + (size_t)(r0 + 8) * ldc + col) = pack_bf16(o10, o11);
            } else {
                float* C = (float*)Cout;
                float2 r0v = *(const float2*)(resid + (size_t)r0 * ldc + col);
                float2 r1v = *(const float2*)(resid + (size_t)(r0 + 8) * ldc + col);
                float2 w0 = {o00 + r0v.x, o01 + r0v.y};
                float2 w1 = {o10 + r1v.x, o11 + r1v.y};
                *(float2*)(C + (size_t)r0 * ldc + col)       = w0;
                *(float2*)(C + (size_t)(r0 + 8) * ldc + col) = w1;
            }
        }
    }
}

// ---------------------------------------------------------------------------
// bf16 tensor-core flash attention.
// 128 q-rows/CTA, 64 keys/tile, 256 threads = 8 warps x 16 q-rows.
// Q,K row-major bf16-pair tiles; V stored TRANSPOSED (dim-major) so PV
// B-fragments are pair-contiguous. P packs straight from S C-fragments
// (no shuffles). fp32 softmax/accum.
// ---------------------------------------------------------------------------
#define QSTR 36    // pair stride
#define QKVP (3 * DD / 2)   // 1536 pairs per qkv row

__global__ void __launch_bounds__(256) attn_mma(const float* __restrict__ mask)
{
    extern __shared__ __align__(16) uint32_t sm[];
    uint32_t* Qs  = sm;                     // 128 rows x 36 pairs
    uint32_t* Ks  = Qs + 128 * QSTR;        // 64 rows x 36
    uint32_t* Vt  = Ks + 64 * QSTR;         // 64 dims x 36 (keypairs)
    float*    Msk = (float*)(Vt + 64 * QSTR);  // 64

    int t = threadIdx.x;
    int lane = t & 31, wid = t >> 5;
    int gid = lane >> 2, tig = lane & 3;
    int b = blockIdx.z, h = blockIdx.y, qt = blockIdx.x;
    int qrow0 = b * SS + qt * 128;
    int qr = wid * 16;

    const uint32_t* qkvp = (const uint32_t*)g_qkv16;
    const uint32_t* qbase = qkvp + (size_t)qrow0 * QKVP + h * (HD / 2);

    // stage Q: 128 rows x 32 pairs = 128*8 = 1024 uint4 (4 pairs each)
    #pragma unroll
    for (int i = 0; i < 4; i++) {
        int idx = t + i * 256;
        int r = idx >> 3, q8 = idx & 7;
        *(uint4*)(Qs + r * QSTR + q8 * 4) =
            *(const uint4*)(qbase + (size_t)r * QKVP + q8 * 4);
    }

    float oacc[8][4];
    #pragma unroll
    for (int nd = 0; nd < 8; nd++)
        #pragma unroll
        for (int r = 0; r < 4; r++) oacc[nd][r] = 0.f;
    float mrow[2] = {-1e30f, -1e30f};
    float lrow[2] = {0.f, 0.f};

    for (int kt = 0; kt < SS / 64; kt++) {
        __syncthreads();
        const uint32_t* kbg = qkvp + (size_t)(b * SS + kt * 64) * QKVP
                              + (DD / 2) + h * (HD / 2);
        const uint32_t* vbg = kbg + (DD / 2);
        // K: 64 rows x 32 pairs = 64*8 = 512 uint4
        #pragma unroll
        for (int i = 0; i < 2; i++) {
            int idx = t + i * 256;
            int r = idx >> 3, q8 = idx & 7;
            *(uint4*)(Ks + r * QSTR + q8 * 4) =
                *(const uint4*)(kbg + (size_t)r * QKVP + q8 * 4);
        }
        // V transposed: read uint4 (= 8 dims) of one key, scatter to Vt[dim][key]
        __nv_bfloat16* vt16 = (__nv_bfloat16*)Vt;
        #pragma unroll
        for (int i = 0; i < 2; i++) {
            int idx = t + i * 256;
            int key = idx >> 3, d8 = idx & 7;
            uint4 vv = *(const uint4*)(vbg + (size_t)key * QKVP + d8 * 4);
            const uint32_t* vp = (const uint32_t*)&vv;
            #pragma unroll
            for (int p = 0; p < 4; p++) {
                __nv_bfloat162 pr = *(__nv_bfloat162*)&vp[p];
                int dim = d8 * 8 + p * 2;
                vt16[(size_t)dim * (QSTR * 2) + key]       = pr.x;
                vt16[(size_t)(dim + 1) * (QSTR * 2) + key] = pr.y;
            }
        }
        if (t < 64) Msk[t] = mask[b * SS + kt * 64 + t];
        __syncthreads();

        // ---- S = Q K^T (bf16 m16n8k16) ----
        float sacc[8][4];
        #pragma unroll
        for (int nt = 0; nt < 8; nt++)
            #pragma unroll
            for (int r = 0; r < 4; r++) sacc[nt][r] = 0.f;

        #pragma unroll
        for (int ks = 0; ks < 4; ks++) {       // 4 k16 steps over 32 pairs
            int kb = ks * 8 + tig;
            uint32_t qa[4];
            const uint32_t* qp = Qs + (qr + gid) * QSTR + kb;
            qa[0] = qp[0];
            qa[1] = qp[8 * QSTR];
            qa[2] = qp[4];
            qa[3] = qp[8 * QSTR + 4];
            #pragma unroll
            for (int nt = 0; nt < 8; nt++) {
                const uint32_t* kp = Ks + (nt * 8 + gid) * QSTR + kb;
                uint32_t kbf[2] = {kp[0], kp[4]};
                mma_bf16(sacc[nt], qa, kbf);
            }
        }

        // ---- online softmax (fp32, C-fragment layout) ----
        {
            float mx0 = mrow[0], mx1 = mrow[1];
            #pragma unroll
            for (int nt = 0; nt < 8; nt++) {
                float mk0 = Msk[nt * 8 + 2 * tig];
                float mk1 = Msk[nt * 8 + 2 * tig + 1];
                float* s = sacc[nt];
                s[0] = s[0] * 0.125f + mk0;
                s[1] = s[1] * 0.125f + mk1;
                s[2] = s[2] * 0.125f + mk0;
                s[3] = s[3] * 0.125f + mk1;
                mx0 = fmaxf(mx0, fmaxf(s[0], s[1]));
                mx1 = fmaxf(mx1, fmaxf(s[2], s[3]));
            }
            mx0 = fmaxf(mx0, __shfl_xor_sync(0xffffffffu, mx0, 1));
            mx0 = fmaxf(mx0, __shfl_xor_sync(0xffffffffu, mx0, 2));
            mx1 = fmaxf(mx1, __shfl_xor_sync(0xffffffffu, mx1, 1));
            mx1 = fmaxf(mx1, __shfl_xor_sync(0xffffffffu, mx1, 2));
            float c0 = __expf(mrow[0] - mx0);
            float c1 = __expf(mrow[1] - mx1);
            mrow[0] = mx0; mrow[1] = mx1;
            float ls0 = 0.f, ls1 = 0.f;
            #pragma unroll
            for (int nt = 0; nt < 8; nt++) {
                float* s = sacc[nt];
                s[0] = __expf(s[0] - mx0);
                s[1] = __expf(s[1] - mx0);
                s[2] = __expf(s[2] - mx1);
                s[3] = __expf(s[3] - mx1);
                ls0 += s[0] + s[1];
                ls1 += s[2] + s[3];
            }
            ls0 += __shfl_xor_sync(0xffffffffu, ls0, 1);
            ls0 += __shfl_xor_sync(0xffffffffu, ls0, 2);
            ls1 += __shfl_xor_sync(0xffffffffu, ls1, 1);
            ls1 += __shfl_xor_sync(0xffffffffu, ls1, 2);
            lrow[0] = lrow[0] * c0 + ls0;
            lrow[1] = lrow[1] * c1 + ls1;
            #pragma unroll
            for (int nd = 0; nd < 8; nd++) {
                float* o = oacc[nd];
                o[0] *= c0; o[1] *= c0; o[2] *= c1; o[3] *= c1;
            }
        }

        // ---- O += P V : pack P straight from C-fragments (no shuffles) ----
        #pragma unroll
        for (int j = 0; j < 4; j++) {          // 4 k16 blocks of 16 keys
            uint32_t pa[4];
            float* s0 = sacc[2 * j];
            float* s1 = sacc[2 * j + 1];
            pa[0] = pack_bf16(s0[0], s0[1]);   // row g,   keypair tig
            pa[1] = pack_bf16(s0[2], s0[3]);   // row g+8, keypair tig
            pa[2] = pack_bf16(s1[0], s1[1]);   // row g,   keypair tig+4
            pa[3] = pack_bf16(s1[2], s1[3]);   // row g+8, keypair tig+4
            #pragma unroll
            for (int nd = 0; nd < 8; nd++) {
                const uint32_t* vp = Vt + (nd * 8 + gid) * QSTR + j * 8 + tig;
                uint32_t vbf[2] = {vp[0], vp[4]};
                mma_bf16(oacc[nd], pa, vbf);
            }
        }
    }

    // ---- epilogue: normalize, store ctx as bf16 ----
    {
        float inv0 = 1.f / lrow[0];
        float inv1 = 1.f / lrow[1];
        int r0 = qrow0 + qr + gid;
        #pragma unroll
        for (int nd = 0; nd < 8; nd++) {
            int col = h * HD + nd * 8 + 2 * tig;
            *(uint32_t*)(g_ctx16 + (size_t)r0 * DD + col) =
                pack_bf16(oacc[nd][0] * inv0, oacc[nd][1] * inv0);
            *(uint32_t*)(g_ctx16 + (size_t)(r0 + 8) * DD + col) =
                pack_bf16(oacc[nd][2] * inv1, oacc[nd][3] * inv1);
        }
    }
}

// ---------------------------------------------------------------------------
// Launcher
// ---------------------------------------------------------------------------
extern "C" void kernel_launch(void* const* d_in, const int* in_sizes, int n_in,
                              void* d_out, int out_size)
{
    const float* hidden = (const float*)d_in[0];
    const float* mask   = (const float*)d_in[1];
    const float* gamma  = (const float*)d_in[2];
    const float* beta   = (const float*)d_in[3];
    const float* wq = (const float*)d_in[4];
    const float* bq = (const float*)d_in[5];
    const float* wk = (const float*)d_in[6];
    const float* bk = (const float*)d_in[7];
    const float* wv = (const float*)d_in[8];
    const float* bv = (const float*)d_in[9];
    const float* wo = (const float*)d_in[10];
    const float* bo = (const float*)d_in[11];
    float* out = (float*)d_out;

    void *p_xn, *p_qkv, *p_ctx, *p_w, *p_bqkv;
    cudaGetSymbolAddress(&p_xn,  g_xn16);
    cudaGetSymbolAddress(&p_qkv, g_qkv16);
    cudaGetSymbolAddress(&p_ctx, g_ctx16);
    cudaGetSymbolAddress(&p_w,   g_w16);
    cudaGetSymbolAddress(&p_bqkv, g_bqkv);
    __nv_bfloat16* xn  = (__nv_bfloat16*)p_xn;
    __nv_bfloat16* qkv = (__nv_bfloat16*)p_qkv;
    __nv_bfloat16* ctx = (__nv_bfloat16*)p_ctx;
    __nv_bfloat16* w16 = (__nv_bfloat16*)p_w;
    float* bqkv = (float*)p_bqkv;

    // 0. Prep: bf16 weights, concat qkv bias
    wprep_kernel<<<4 * DD * DD / 4 / 256, 256>>>(wq, wk, wv, wo, w16);
    bprep_kernel<<<3 * DD / 256, 256>>>(bq, bk, bv, bqkv);

    // 1. LayerNorm (bf16 output)
    ln_kernel<<<ROWS, 256>>>(hidden, gamma, beta, xn);

    // 2. Fused QKV projection: [4096,1024] @ [3072,1024]^T -> bf16
    cudaFuncSetAttribute(gemm_mma<true>,
                         cudaFuncAttributeMaxDynamicSharedMemorySize, GSMEM_BYTES);
    cudaFuncSetAttribute(gemm_mma<false>,
                         cudaFuncAttributeMaxDynamicSharedMemorySize, GSMEM_BYTES);
    gemm_mma<true><<<dim3(3 * DD / 256, ROWS / 128), 256, GSMEM_BYTES>>>(
        (const uint32_t*)xn, (const uint32_t*)w16, bqkv, nullptr, qkv, 3 * DD);

    // 3. bf16 tensor-core flash attention
    int smem = (128 * QSTR + 64 * QSTR * 2) * 4 + 64 * 4;
    cudaFuncSetAttribute(attn_mma, cudaFuncAttributeMaxDynamicSharedMemorySize, smem);
    attn_mma<<<dim3(SS / 128, HH, BB), 256, smem>>>(mask);

    // 4. Output projection + bias + residual (fp32 out)
    gemm_mma<false><<<dim3(DD / 256, ROWS / 128), 256, GSMEM_BYTES>>>(
        (const uint32_t*)ctx, (const uint32_t*)(w16 + (size_t)3 * DD * DD),
        bo, hidden, out, DD);
}

// round 11
// speedup vs baseline: 8.2878x; 1.0146x over previous
#include <cuda_runtime.h>
#include <cuda_bf16.h>
#include <cstdint>
#include <math.h>

#define BB 2
#define SS 2048
#define DD 1024
#define HH 16
#define HD 64
#define ROWS (BB*SS)

// Scratch (static device globals — no runtime allocation)
__device__ __nv_bfloat16 g_xn16[ROWS * DD];
__device__ __nv_bfloat16 g_qkv16[ROWS * 3 * DD];
__device__ __nv_bfloat16 g_ctx16[ROWS * DD];
__device__ __nv_bfloat16 g_w16[4 * DD * DD];   // bf16 wq,wk,wv,wo
__device__ float g_bqkv[3 * DD];

// ---------------------------------------------------------------------------
// helpers
// ---------------------------------------------------------------------------
__device__ __forceinline__ uint32_t smem_u32(const void* p) {
    uint32_t a;
    asm("{ .reg .u64 t; cvta.to.shared.u64 t, %1; cvt.u32.u64 %0, t; }"
        : "=r"(a) : "l"(p));
    return a;
}

// pack two fp32 -> bf16x2 (lo = first arg, hi = second), round-to-nearest
__device__ __forceinline__ uint32_t pack_bf16(float lo, float hi) {
    uint32_t d;
    asm("cvt.rn.bf16x2.f32 %0, %1, %2;" : "=r"(d) : "f"(hi), "f"(lo));
    return d;
}

#define CP_ASYNC16(smem_addr, gptr) \
    asm volatile("cp.async.cg.shared.global [%0], [%1], 16;" \
                 :: "r"(smem_addr), "l"(gptr) : "memory")
#define CP_COMMIT() asm volatile("cp.async.commit_group;" ::: "memory")
#define CP_WAIT(N)  asm volatile("cp.async.wait_group %0;" :: "n"(N) : "memory")

#define LDSM_X4(r0, r1, r2, r3, addr) \
    asm volatile("ldmatrix.sync.aligned.m8n8.x4.shared.b16 {%0,%1,%2,%3}, [%4];" \
                 : "=r"(r0), "=r"(r1), "=r"(r2), "=r"(r3) : "r"(addr))

__device__ __forceinline__ void mma_bf16(float* c, const uint32_t* a, const uint32_t* b) {
    asm volatile(
        "mma.sync.aligned.m16n8k16.row.col.f32.bf16.bf16.f32 "
        "{%0,%1,%2,%3}, {%4,%5,%6,%7}, {%8,%9}, {%0,%1,%2,%3};"
        : "+f"(c[0]), "+f"(c[1]), "+f"(c[2]), "+f"(c[3])
        : "r"(a[0]), "r"(a[1]), "r"(a[2]), "r"(a[3]), "r"(b[0]), "r"(b[1]));
}

// ---------------------------------------------------------------------------
// Weight prep: fp32 -> bf16 (rn) for all 4 weight matrices
// ---------------------------------------------------------------------------
__global__ void __launch_bounds__(256) wprep_kernel(
    const float* __restrict__ wq, const float* __restrict__ wk,
    const float* __restrict__ wv, const float* __restrict__ wo,
    __nv_bfloat16* __restrict__ dst)
{
    int i = blockIdx.x * 256 + threadIdx.x;        // float4 index
    const float* srcs[4] = {wq, wk, wv, wo};
    int which = i / (DD * DD / 4);
    int off   = i % (DD * DD / 4);
    float4 v = ((const float4*)srcs[which])[off];
    uint2 o;
    o.x = pack_bf16(v.x, v.y);
    o.y = pack_bf16(v.z, v.w);
    ((uint2*)dst)[i] = o;
}

__global__ void __launch_bounds__(256) bprep_kernel(
    const float* __restrict__ bq, const float* __restrict__ bk,
    const float* __restrict__ bv, float* __restrict__ dst)
{
    int i = blockIdx.x * 256 + threadIdx.x;        // 0..3071
    const float* s = (i < DD) ? bq : ((i < 2 * DD) ? bk : bv);
    dst[i] = s[i & (DD - 1)];
}

// ---------------------------------------------------------------------------
// LayerNorm: one block per row; output bf16
// ---------------------------------------------------------------------------
__global__ void __launch_bounds__(256) ln_kernel(
    const float* __restrict__ x, const float* __restrict__ gamma,
    const float* __restrict__ beta, __nv_bfloat16* __restrict__ out)
{
    int row = blockIdx.x;
    int t = threadIdx.x;
    float4 v = ((const float4*)(x + (size_t)row * DD))[t];
    float s  = v.x + v.y + v.z + v.w;
    float ss = v.x*v.x + v.y*v.y + v.z*v.z + v.w*v.w;

    #pragma unroll
    for (int o = 16; o; o >>= 1) {
        s  += __shfl_xor_sync(0xffffffffu, s,  o);
        ss += __shfl_xor_sync(0xffffffffu, ss, o);
    }
    __shared__ float rs[8], rss[8];
    int w = t >> 5;
    if ((t & 31) == 0) { rs[w] = s; rss[w] = ss; }
    __syncthreads();
    if (t < 32) {
        float a  = (t < 8) ? rs[t]  : 0.f;
        float aa = (t < 8) ? rss[t] : 0.f;
        #pragma unroll
        for (int o = 4; o; o >>= 1) {
            a  += __shfl_xor_sync(0xffffffffu, a,  o);
            aa += __shfl_xor_sync(0xffffffffu, aa, o);
        }
        if (t == 0) { rs[0] = a; rss[0] = aa; }
    }
    __syncthreads();
    float mean = rs[0] * (1.0f / DD);
    float var  = rss[0] * (1.0f / DD) - mean * mean;
    float rstd = rsqrtf(var + 1e-12f);

    float4 g  = ((const float4*)gamma)[t];
    float4 bt = ((const float4*)beta)[t];
    uint2 o;
    o.x = pack_bf16((v.x - mean) * rstd * g.x + bt.x,
                    (v.y - mean) * rstd * g.y + bt.y);
    o.y = pack_bf16((v.z - mean) * rstd * g.z + bt.z,
                    (v.w - mean) * rstd * g.w + bt.w);
    ((uint2*)(out + (size_t)row * DD))[t] = o;
}

// ---------------------------------------------------------------------------
// bf16 mma.sync GEMM-NT with ldmatrix fragment loads.
// Block 128x256, 8 warps (2x4) of 64x64. 3-stage cp.async, dynamic smem.
// ---------------------------------------------------------------------------
#define SKW 20
#define GSTG 3
#define GA_STAGE (128 * SKW)
#define GB_STAGE (256 * SKW)
#define GSMEM_BYTES (GSTG * (GA_STAGE + GB_STAGE) * 4)
#define KP (DD / 2)            // 512 pairs per row

template<bool OUT_BF16>
__global__ void __launch_bounds__(256) gemm_mma(
    const uint32_t* __restrict__ A, const uint32_t* __restrict__ W,
    const float* __restrict__ bias, const float* __restrict__ resid,
    void* __restrict__ Cout, int ldc)
{
    extern __shared__ __align__(16) uint32_t gsm[];
    uint32_t* sAb = gsm;
    uint32_t* sBb = gsm + GSTG * GA_STAGE;

    int tid  = threadIdx.x;
    int lane = tid & 31;
    int wid  = tid >> 5;
    int wm = (wid & 1) * 64;
    int wn = (wid >> 1) * 64;
    int rowBase = blockIdx.y * 128;
    int colBase = blockIdx.x * 256;
    int gid = lane >> 2;
    int tig = lane & 3;

    // ldmatrix lane->address components (in pairs)
    int a_row = lane & 15;                         // A: matrix row select
    int a_k4  = (lane >> 4) * 4;                   // A: 0 / +4 pairs (k+8 elems)
    int b_row = ((lane >> 4) & 1) * 8 + (lane & 7);// B: n-row within 16-row pair
    int b_k4  = ((lane >> 3) & 1) * 4;             // B: 0 / +4 pairs

    int lrow = tid >> 2;          // 0..63
    int lc4  = tid & 3;           // 0..3 (16B = 4 pairs each)
    const uint32_t* gA0 = A + (size_t)(rowBase + lrow) * KP + lc4 * 4;
    const uint32_t* gA1 = gA0 + (size_t)64 * KP;
    const uint32_t* gB0 = W + (size_t)(colBase + lrow) * KP + lc4 * 4;
    const uint32_t* gB1 = gB0 + (size_t)64 * KP;
    const uint32_t* gB2 = gB0 + (size_t)128 * KP;
    const uint32_t* gB3 = gB0 + (size_t)192 * KP;

    uint32_t offR0 = (uint32_t)((lrow * SKW + lc4 * 4) * 4);
    uint32_t offR1 = (uint32_t)(((lrow + 64) * SKW + lc4 * 4) * 4);

    uint32_t sawA[GSTG], sawB[GSTG];
    #pragma unroll
    for (int s = 0; s < GSTG; s++) {
        sawA[s] = smem_u32(sAb + s * GA_STAGE);
        sawB[s] = smem_u32(sBb + s * GB_STAGE);
    }

    float acc[4][8][4];
    #pragma unroll
    for (int mt = 0; mt < 4; mt++)
        #pragma unroll
        for (int nt = 0; nt < 8; nt++)
            #pragma unroll
            for (int r = 0; r < 4; r++) acc[mt][nt][r] = 0.f;

    const int NCHUNK = KP / 16;   // 32

    #pragma unroll
    for (int p = 0; p < 2; p++) {
        int k0 = p * 16;
        CP_ASYNC16(sawA[p] + offR0, gA0 + k0);
        CP_ASYNC16(sawA[p] + offR1, gA1 + k0);
        CP_ASYNC16(sawB[p] + offR0, gB0 + k0);
        CP_ASYNC16(sawB[p] + offR1, gB1 + k0);
        CP_ASYNC16(sawB[p] + offR0 + 128 * SKW * 4, gB2 + k0);
        CP_ASYNC16(sawB[p] + offR1 + 128 * SKW * 4, gB3 + k0);
        CP_COMMIT();
    }

    for (int c = 0; c < NCHUNK; c++) {
        if (c + 2 < NCHUNK) {
            int s = (c + 2) % GSTG;
            int k0 = (c + 2) * 16;
            CP_ASYNC16(sawA[s] + offR0, gA0 + k0);
            CP_ASYNC16(sawA[s] + offR1, gA1 + k0);
            CP_ASYNC16(sawB[s] + offR0, gB0 + k0);
            CP_ASYNC16(sawB[s] + offR1, gB1 + k0);
            CP_ASYNC16(sawB[s] + offR0 + 128 * SKW * 4, gB2 + k0);
            CP_ASYNC16(sawB[s] + offR1 + 128 * SKW * 4, gB3 + k0);
        }
        CP_COMMIT();
        CP_WAIT(2);
        __syncthreads();

        uint32_t paw = sawA[c % GSTG];
        uint32_t pbw = sawB[c % GSTG];
        #pragma unroll
        for (int ks = 0; ks < 2; ks++) {
            uint32_t kbyte = (uint32_t)(ks * 8 * 4);
            uint32_t af[4][4];
            #pragma unroll
            for (int mt = 0; mt < 4; mt++) {
                uint32_t ad = paw + ((wm + mt * 16 + a_row) * SKW + a_k4) * 4 + kbyte;
                LDSM_X4(af[mt][0], af[mt][1], af[mt][2], af[mt][3], ad);
            }
            uint32_t bf[8][2];
            #pragma unroll
            for (int j = 0; j < 4; j++) {
                uint32_t bd = pbw + ((wn + j * 16 + b_row) * SKW + b_k4) * 4 + kbyte;
                LDSM_X4(bf[2 * j][0], bf[2 * j][1], bf[2 * j + 1][0], bf[2 * j + 1][1], bd);
            }
            #pragma unroll
            for (int mt = 0; mt < 4; mt++)
                #pragma unroll
                for (int nt = 0; nt < 8; nt++)
                    mma_bf16(acc[mt][nt], af[mt], bf[nt]);
        }
        __syncthreads();
    }

    #pragma unroll
    for (int mt = 0; mt < 4; mt++) {
        int r0 = rowBase + wm + mt * 16 + gid;
        #pragma unroll
        for (int nt = 0; nt < 8; nt++) {
            int col = colBase + wn + nt * 8 + tig * 2;
            float2 b2 = *(const float2*)(bias + col);
            float o00 = acc[mt][nt][0] + b2.x, o01 = acc[mt][nt][1] + b2.y;
            float o10 = acc[mt][nt][2] + b2.x, o11 = acc[mt][nt][3] + b2.y;
            if (OUT_BF16) {
                __nv_bfloat16* C16 = (__nv_bfloat16*)Cout;
                *(uint32_t*)(C16 + (size_t)r0 * ldc + col)       = pack_bf16(o00, o01);
                *(uint32_t*)(C16 + (size_t)(r0 + 8) * ldc + col) = pack_bf16(o10, o11);
            } else {
                float* C = (float*)Cout;
                float2 r0v = *(const float2*)(resid + (size_t)r0 * ldc + col);
                float2 r1v = *(const float2*)(resid + (size_t)(r0 + 8) * ldc + col);
                float2 w0 = {o00 + r0v.x, o01 + r0v.y};
                float2 w1 = {o10 + r1v.x, o11 + r1v.y};
                *(float2*)(C + (size_t)r0 * ldc + col)       = w0;
                *(float2*)(C + (size_t)(r0 + 8) * ldc + col) = w1;
            }
        }
    }
}

// ---------------------------------------------------------------------------
// bf16 tensor-core flash attention with ldmatrix fragment loads.
// 128 q-rows/CTA, 64 keys/tile, 256 threads = 8 warps x 16 q-rows.
// ---------------------------------------------------------------------------
#define QSTR 36    // pair stride
#define QKVP (3 * DD / 2)   // 1536 pairs per qkv row

__global__ void __launch_bounds__(256) attn_mma(const float* __restrict__ mask)
{
    extern __shared__ __align__(16) uint32_t sm[];
    uint32_t* Qs  = sm;                     // 128 rows x 36 pairs
    uint32_t* Ks  = Qs + 128 * QSTR;        // 64 rows x 36
    uint32_t* Vt  = Ks + 64 * QSTR;         // 64 dims x 36 (keypairs)
    float*    Msk = (float*)(Vt + 64 * QSTR);  // 64

    int t = threadIdx.x;
    int lane = t & 31, wid = t >> 5;
    int gid = lane >> 2, tig = lane & 3;
    int b = blockIdx.z, h = blockIdx.y, qt = blockIdx.x;
    int qrow0 = b * SS + qt * 128;
    int qr = wid * 16;

    int a_row = lane & 15;
    int a_k4  = (lane >> 4) * 4;
    int b_row = ((lane >> 4) & 1) * 8 + (lane & 7);
    int b_k4  = ((lane >> 3) & 1) * 4;

    uint32_t sawQ = smem_u32(Qs);
    uint32_t sawK = smem_u32(Ks);
    uint32_t sawV = smem_u32(Vt);

    const uint32_t* qkvp = (const uint32_t*)g_qkv16;
    const uint32_t* qbase = qkvp + (size_t)qrow0 * QKVP + h * (HD / 2);

    // stage Q: 128 rows x 32 pairs = 1024 uint4 (4 pairs each)
    #pragma unroll
    for (int i = 0; i < 4; i++) {
        int idx = t + i * 256;
        int r = idx >> 3, q8 = idx & 7;
        *(uint4*)(Qs + r * QSTR + q8 * 4) =
            *(const uint4*)(qbase + (size_t)r * QKVP + q8 * 4);
    }

    float oacc[8][4];
    #pragma unroll
    for (int nd = 0; nd < 8; nd++)
        #pragma unroll
        for (int r = 0; r < 4; r++) oacc[nd][r] = 0.f;
    float mrow[2] = {-1e30f, -1e30f};
    float lrow[2] = {0.f, 0.f};

    for (int kt = 0; kt < SS / 64; kt++) {
        __syncthreads();
        const uint32_t* kbg = qkvp + (size_t)(b * SS + kt * 64) * QKVP
                              + (DD / 2) + h * (HD / 2);
        const uint32_t* vbg = kbg + (DD / 2);
        // K: 64 rows x 32 pairs = 512 uint4
        #pragma unroll
        for (int i = 0; i < 2; i++) {
            int idx = t + i * 256;
            int r = idx >> 3, q8 = idx & 7;
            *(uint4*)(Ks + r * QSTR + q8 * 4) =
                *(const uint4*)(kbg + (size_t)r * QKVP + q8 * 4);
        }
        // V transposed: read uint4 (= 8 dims) of one key, scatter to Vt[dim][key]
        __nv_bfloat16* vt16 = (__nv_bfloat16*)Vt;
        #pragma unroll
        for (int i = 0; i < 2; i++) {
            int idx = t + i * 256;
            int key = idx >> 3, d8 = idx & 7;
            uint4 vv = *(const uint4*)(vbg + (size_t)key * QKVP + d8 * 4);
            const uint32_t* vp = (const uint32_t*)&vv;
            #pragma unroll
            for (int p = 0; p < 4; p++) {
                __nv_bfloat162 pr = *(__nv_bfloat162*)&vp[p];
                int dim = d8 * 8 + p * 2;
                vt16[(size_t)dim * (QSTR * 2) + key]       = pr.x;
                vt16[(size_t)(dim + 1) * (QSTR * 2) + key] = pr.y;
            }
        }
        if (t < 64) Msk[t] = mask[b * SS + kt * 64 + t];
        __syncthreads();

        // ---- S = Q K^T (bf16 m16n8k16, ldmatrix) ----
        float sacc[8][4];
        #pragma unroll
        for (int nt = 0; nt < 8; nt++)
            #pragma unroll
            for (int r = 0; r < 4; r++) sacc[nt][r] = 0.f;

        #pragma unroll
        for (int ks = 0; ks < 4; ks++) {       // 4 k16 steps over 32 pairs
            uint32_t kbyte = (uint32_t)(ks * 8 * 4);
            uint32_t qa[4];
            {
                uint32_t ad = sawQ + ((qr + a_row) * QSTR + a_k4) * 4 + kbyte;
                LDSM_X4(qa[0], qa[1], qa[2], qa[3], ad);
            }
            uint32_t kf[8][2];
            #pragma unroll
            for (int j = 0; j < 4; j++) {
                uint32_t kd = sawK + ((j * 16 + b_row) * QSTR + b_k4) * 4 + kbyte;
                LDSM_X4(kf[2 * j][0], kf[2 * j][1], kf[2 * j + 1][0], kf[2 * j + 1][1], kd);
            }
            #pragma unroll
            for (int nt = 0; nt < 8; nt++)
                mma_bf16(sacc[nt], qa, kf[nt]);
        }

        // ---- online softmax (fp32, C-fragment layout) ----
        {
            float mx0 = mrow[0], mx1 = mrow[1];
            #pragma unroll
            for (int nt = 0; nt < 8; nt++) {
                float mk0 = Msk[nt * 8 + 2 * tig];
                float mk1 = Msk[nt * 8 + 2 * tig + 1];
                float* s = sacc[nt];
                s[0] = s[0] * 0.125f + mk0;
                s[1] = s[1] * 0.125f + mk1;
                s[2] = s[2] * 0.125f + mk0;
                s[3] = s[3] * 0.125f + mk1;
                mx0 = fmaxf(mx0, fmaxf(s[0], s[1]));
                mx1 = fmaxf(mx1, fmaxf(s[2], s[3]));
            }
            mx0 = fmaxf(mx0, __shfl_xor_sync(0xffffffffu, mx0, 1));
            mx0 = fmaxf(mx0, __shfl_xor_sync(0xffffffffu, mx0, 2));
            mx1 = fmaxf(mx1, __shfl_xor_sync(0xffffffffu, mx1, 1));
            mx1 = fmaxf(mx1, __shfl_xor_sync(0xffffffffu, mx1, 2));
            float c0 = __expf(mrow[0] - mx0);
            float c1 = __expf(mrow[1] - mx1);
            mrow[0] = mx0; mrow[1] = mx1;
            float ls0 = 0.f, ls1 = 0.f;
            #pragma unroll
            for (int nt = 0; nt < 8; nt++) {
                float* s = sacc[nt];
                s[0] = __expf(s[0] - mx0);
                s[1] = __expf(s[1] - mx0);
                s[2] = __expf(s[2] - mx1);
                s[3] = __expf(s[3] - mx1);
                ls0 += s[0] + s[1];
                ls1 += s[2] + s[3];
            }
            ls0 += __shfl_xor_sync(0xffffffffu, ls0, 1);
            ls0 += __shfl_xor_sync(0xffffffffu, ls0, 2);
            ls1 += __shfl_xor_sync(0xffffffffu, ls1, 1);
            ls1 += __shfl_xor_sync(0xffffffffu, ls1, 2);
            lrow[0] = lrow[0] * c0 + ls0;
            lrow[1] = lrow[1] * c1 + ls1;
            #pragma unroll
            for (int nd = 0; nd < 8; nd++) {
                float* o = oacc[nd];
                o[0] *= c0; o[1] *= c0; o[2] *= c1; o[3] *= c1;
            }
        }

        // ---- O += P V : pack P from C-fragments, V frags via ldmatrix ----
        #pragma unroll
        for (int j = 0; j < 4; j++) {          // 4 k16 blocks of 16 keys
            uint32_t pa[4];
            float* s0 = sacc[2 * j];
            float* s1 = sacc[2 * j + 1];
            pa[0] = pack_bf16(s0[0], s0[1]);   // row g,   keypair tig
            pa[1] = pack_bf16(s0[2], s0[3]);   // row g+8, keypair tig
            pa[2] = pack_bf16(s1[0], s1[1]);   // row g,   keypair tig+4
            pa[3] = pack_bf16(s1[2], s1[3]);   // row g+8, keypair tig+4
            uint32_t vbf[8][2];
            #pragma unroll
            for (int jj = 0; jj < 4; jj++) {
                uint32_t vd = sawV + ((jj * 16 + b_row) * QSTR + j * 8 + b_k4) * 4;
                LDSM_X4(vbf[2 * jj][0], vbf[2 * jj][1],
                        vbf[2 * jj + 1][0], vbf[2 * jj + 1][1], vd);
            }
            #pragma unroll
            for (int nd = 0; nd < 8; nd++)
                mma_bf16(oacc[nd], pa, vbf[nd]);
        }
    }

    // ---- epilogue: normalize, store ctx as bf16 ----
    {
        float inv0 = 1.f / lrow[0];
        float inv1 = 1.f / lrow[1];
        int r0 = qrow0 + qr + gid;
        #pragma unroll
        for (int nd = 0; nd < 8; nd++) {
            int col = h * HD + nd * 8 + 2 * tig;
            *(uint32_t*)(g_ctx16 + (size_t)r0 * DD + col) =
                pack_bf16(oacc[nd][0] * inv0, oacc[nd][1] * inv0);
            *(uint32_t*)(g_ctx16 + (size_t)(r0 + 8) * DD + col) =
                pack_bf16(oacc[nd][2] * inv1, oacc[nd][3] * inv1);
        }
    }
}

// ---------------------------------------------------------------------------
// Launcher
// ---------------------------------------------------------------------------
extern "C" void kernel_launch(void* const* d_in, const int* in_sizes, int n_in,
                              void* d_out, int out_size)
{
    const float* hidden = (const float*)d_in[0];
    const float* mask   = (const float*)d_in[1];
    const float* gamma  = (const float*)d_in[2];
    const float* beta   = (const float*)d_in[3];
    const float* wq = (const float*)d_in[4];
    const float* bq = (const float*)d_in[5];
    const float* wk = (const float*)d_in[6];
    const float* bk = (const float*)d_in[7];
    const float* wv = (const float*)d_in[8];
    const float* bv = (const float*)d_in[9];
    const float* wo = (const float*)d_in[10];
    const float* bo = (const float*)d_in[11];
    float* out = (float*)d_out;

    void *p_xn, *p_qkv, *p_ctx, *p_w, *p_bqkv;
    cudaGetSymbolAddress(&p_xn,  g_xn16);
    cudaGetSymbolAddress(&p_qkv, g_qkv16);
    cudaGetSymbolAddress(&p_ctx, g_ctx16);
    cudaGetSymbolAddress(&p_w,   g_w16);
    cudaGetSymbolAddress(&p_bqkv, g_bqkv);
    __nv_bfloat16* xn  = (__nv_bfloat16*)p_xn;
    __nv_bfloat16* qkv = (__nv_bfloat16*)p_qkv;
    __nv_bfloat16* ctx = (__nv_bfloat16*)p_ctx;
    __nv_bfloat16* w16 = (__nv_bfloat16*)p_w;
    float* bqkv = (float*)p_bqkv;

    // 0. Prep: bf16 weights, concat qkv bias
    wprep_kernel<<<4 * DD * DD / 4 / 256, 256>>>(wq, wk, wv, wo, w16);
    bprep_kernel<<<3 * DD / 256, 256>>>(bq, bk, bv, bqkv);

    // 1. LayerNorm (bf16 output)
    ln_kernel<<<ROWS, 256>>>(hidden, gamma, beta, xn);

    // 2. Fused QKV projection: [4096,1024] @ [3072,1024]^T -> bf16
    cudaFuncSetAttribute(gemm_mma<true>,
                         cudaFuncAttributeMaxDynamicSharedMemorySize, GSMEM_BYTES);
    cudaFuncSetAttribute(gemm_mma<false>,
                         cudaFuncAttributeMaxDynamicSharedMemorySize, GSMEM_BYTES);
    gemm_mma<true><<<dim3(3 * DD / 256, ROWS / 128), 256, GSMEM_BYTES>>>(
        (const uint32_t*)xn, (const uint32_t*)w16, bqkv, nullptr, qkv, 3 * DD);

    // 3. bf16 tensor-core flash attention
    int smem = (128 * QSTR + 64 * QSTR * 2) * 4 + 64 * 4;
    cudaFuncSetAttribute(attn_mma, cudaFuncAttributeMaxDynamicSharedMemorySize, smem);
    attn_mma<<<dim3(SS / 128, HH, BB), 256, smem>>>(mask);

    // 4. Output projection + bias + residual (fp32 out)
    gemm_mma<false><<<dim3(DD / 256, ROWS / 128), 256, GSMEM_BYTES>>>(
        (const uint32_t*)ctx, (const uint32_t*)(w16 + (size_t)3 * DD * DD),
        bo, hidden, out, DD);
}